// round 9
// baseline (speedup 1.0000x reference)
#include <cuda_runtime.h>
#include <cuda_fp16.h>
#include <cstdint>
#include <cstddef>

// BahdanauAttention B=16, T=8192, D=256, U=256 fp32.
// Baseline-PTX (ptxas sm_100): fp16 mma.sync + ldmatrix, persistent fused kernel,
// 256 threads, double accumulator: tile i's MMA overlaps tile i-1's epilogue/
// context tail and tile i+1's staging. values read exactly once from DRAM.

#define Bn 16
#define Tn 8192
#define Dn 256
#define Un 256
#define TM 64                       // score tile M
#define TPB 128                     // tiles per batch
#define NTILES (Bn * TPB)           // 2048
#define GRID_SCORE 148

__device__ float g_escore[Bn * Tn];        // exp(score)
__device__ float g_biasq[Bn * Un];
__device__ float g_zp[NTILES * 2];         // per-tile partial sums of exp
__device__ float g_partial[NTILES * Dn];   // per-tile unnormalized context partials

// ---------------- helpers ----------------

__device__ __forceinline__ __half2 htanh2(__half2 x) {
    uint32_t xi = *(uint32_t*)&x, yo;
    asm("tanh.approx.f16x2 %0, %1;" : "=r"(yo) : "r"(xi));
    return *(__half2*)&yo;
}

__device__ __forceinline__ uint32_t pack_half2(float x, float y) {
    __half2 h = __floats2half2_rn(x, y);
    return *(uint32_t*)&h;
}

__device__ __forceinline__ uint32_t smem_u32(const void* p) {
    uint32_t a;
    asm("{ .reg .u64 t; cvta.to.shared.u64 t, %1; cvt.u32.u64 %0, t; }" : "=r"(a) : "l"(p));
    return a;
}

__device__ __forceinline__ void mma_fp16(float* c, const uint32_t* a, uint32_t b0, uint32_t b1) {
    asm volatile(
        "mma.sync.aligned.m16n8k16.row.col.f32.f16.f16.f32 "
        "{%0,%1,%2,%3},{%4,%5,%6,%7},{%8,%9},{%0,%1,%2,%3};"
        : "+f"(c[0]), "+f"(c[1]), "+f"(c[2]), "+f"(c[3])
        : "r"(a[0]), "r"(a[1]), "r"(a[2]), "r"(a[3]), "r"(b0), "r"(b1));
}

#define LDSM4(r, addr) \
    asm volatile("ldmatrix.sync.aligned.m8n8.x4.shared.b16 {%0,%1,%2,%3}, [%4];" \
                 : "=r"((r)[0]), "=r"((r)[1]), "=r"((r)[2]), "=r"((r)[3]) : "r"(addr))

// ---------------- smem layout (bytes) ----------------
#define SAW 132
#define ABUF_BYTES 33792                    // 64 rows x 132 words x 4B
#define SM_B (2 * ABUF_BYTES)               // 67584
#define SM_SROW (SM_B + 135168)             // 202752 : 64 x 4 floats
#define SM_SES (SM_SROW + 1024)             // 203776 : 64 floats
#define SM_SPART (SM_SES + 256)             // 204032 : 2 x 128 float2
#define SM_TOTAL (SM_SPART + 2048)          // 206080

// ---------------- kernel 0: biasq[b,u] = W1_b + W2_b + query@W2 ----------------

__global__ __launch_bounds__(256)
void projq_kernel(const float* __restrict__ query, const float* __restrict__ W2,
                  const float* __restrict__ W2b, const float* __restrict__ W1b) {
    const int b = blockIdx.y;
    const int u0 = blockIdx.x * 16;
    const int tid = threadIdx.x;
    const int ul = tid & 15, dpart = tid >> 4;

    __shared__ float q[Dn];
    __shared__ float part[16][17];

    if (tid < Dn) q[tid] = query[b * Dn + tid];
    __syncthreads();

    const int u = u0 + ul;
    float acc = 0.f;
#pragma unroll
    for (int i = 0; i < 16; ++i) {
        int d = dpart * 16 + i;
        acc += q[d] * __ldg(W2 + (size_t)d * Un + u);
    }
    part[dpart][ul] = acc;
    __syncthreads();

    if (tid < 16) {
        float s = 0.f;
#pragma unroll
        for (int p = 0; p < 16; ++p) s += part[p][tid];
        int uu = u0 + tid;
        g_biasq[b * Un + uu] = s + W2b[uu] + W1b[uu];
    }
}

// ---------------- kernel 1: persistent fused score+context kernel ----------------
// 256 threads (8 warps). Warp (mwarp=wid&1 -> 32 rows, nwarp=wid>>1 -> 64 cols).
// Iteration it: retire acc->pacc, MMA tile(it), tail of tile(it-1), stage tile(it+1).

__global__ __launch_bounds__(256, 1)
void score_kernel(const float* __restrict__ values, const float* __restrict__ W1,
                  const float* __restrict__ Vw) {
    extern __shared__ char smem[];
    uint32_t* sA = (uint32_t*)smem;
    uint32_t* sB = (uint32_t*)(smem + SM_B);
    float* srow = (float*)(smem + SM_SROW);
    float* ses = (float*)(smem + SM_SES);
    float2* spart = (float2*)(smem + SM_SPART);

    const int tid = threadIdx.x;
    const int wid = tid >> 5, lane = tid & 31;
    const int mwarp = wid & 1, nwarp = wid >> 1;
    const int g = lane >> 2, tig = lane & 3;

    // Stage B once: W1[k][u] -> sB[u][kp] (half2 of k-pair).
#pragma unroll 4
    for (int i = tid; i < 256 * 128; i += 256) {
        int u = i & 255, kp = i >> 8;
        float x0 = __ldg(W1 + (size_t)(2 * kp) * Un + u);
        float x1 = __ldg(W1 + (size_t)(2 * kp + 1) * Un + u);
        sB[u * SAW + kp] = pack_half2(x0, x1);
    }

    const uint32_t sbA = smem_u32(sA), sbB = smem_u32(sB);
    const int t4 = lane >> 3, row_in = lane & 7;
    uint32_t adA[2];
#pragma unroll
    for (int mt = 0; mt < 2; ++mt) {
        int r = mwarp * 32 + mt * 16 + ((t4 & 1) << 3) + row_in;
        adA[mt] = sbA + (uint32_t)((r * SAW + ((t4 >> 1) << 2)) << 2);
    }
    uint32_t adB[4];
#pragma unroll
    for (int np = 0; np < 4; ++np) {
        int u = nwarp * 64 + np * 16 + ((t4 >> 1) << 3) + row_in;
        adB[np] = sbB + (uint32_t)((u * SAW + ((t4 & 1) << 2)) << 2);
    }

    // Prologue: stage first tile into buf0 (float4 loads, uint2 stores).
    {
        const int tile = blockIdx.x;
        const float4* v4 = (const float4*)(values + ((size_t)(tile >> 7) * Tn + (tile & 127) * TM) * Dn);
        uint2* dst = (uint2*)sA;
#pragma unroll
        for (int j = 0; j < 16; ++j) {
            int i = tid + j * 256;
            float4 x = __ldg(v4 + i);
            dst[(i >> 6) * 66 + (i & 63)] = make_uint2(pack_half2(x.x, x.y), pack_half2(x.z, x.w));
        }
    }
    __syncthreads();

    const int c2 = tid & 127, grp = tid >> 7;
    const int ncta = (NTILES - blockIdx.x + GRID_SCORE - 1) / GRID_SCORE;

    float acc[2][8][4], pacc[2][8][4];

    for (int it = 0; it <= ncta; ++it) {
        const int tile = blockIdx.x + it * GRID_SCORE;
        const bool havec = it < ncta;

        // Retire previous accumulators (stalls until prior tile's HMMAs drain).
        if (it > 0) {
#pragma unroll
            for (int mt = 0; mt < 2; ++mt)
#pragma unroll
                for (int nt = 0; nt < 8; ++nt)
#pragma unroll
                    for (int q = 0; q < 4; ++q) pacc[mt][nt][q] = acc[mt][nt][q];
        }
#pragma unroll
        for (int mt = 0; mt < 2; ++mt)
#pragma unroll
            for (int nt = 0; nt < 8; ++nt)
#pragma unroll
                for (int q = 0; q < 4; ++q) acc[mt][nt][q] = 0.f;

        // Issue this tile's MMAs (tensor pipe runs ~8K cyc; everything below overlaps).
        if (havec) {
            const uint32_t abase = (uint32_t)((it & 1) * ABUF_BYTES);
#pragma unroll
            for (int ks = 0; ks < 16; ++ks) {
                const uint32_t ko = (uint32_t)ks * 32;
                uint32_t a0[4], a1[4], b0[4], b1[4], b2[4], b3[4];
                LDSM4(a0, adA[0] + abase + ko);
                LDSM4(a1, adA[1] + abase + ko);
                LDSM4(b0, adB[0] + ko);
                LDSM4(b1, adB[1] + ko);
                LDSM4(b2, adB[2] + ko);
                LDSM4(b3, adB[3] + ko);
                mma_fp16(acc[0][0], a0, b0[0], b0[1]);
                mma_fp16(acc[1][0], a1, b0[0], b0[1]);
                mma_fp16(acc[0][1], a0, b0[2], b0[3]);
                mma_fp16(acc[1][1], a1, b0[2], b0[3]);
                mma_fp16(acc[0][2], a0, b1[0], b1[1]);
                mma_fp16(acc[1][2], a1, b1[0], b1[1]);
                mma_fp16(acc[0][3], a0, b1[2], b1[3]);
                mma_fp16(acc[1][3], a1, b1[2], b1[3]);
                mma_fp16(acc[0][4], a0, b2[0], b2[1]);
                mma_fp16(acc[1][4], a1, b2[0], b2[1]);
                mma_fp16(acc[0][5], a0, b2[2], b2[3]);
                mma_fp16(acc[1][5], a1, b2[2], b2[3]);
                mma_fp16(acc[0][6], a0, b3[0], b3[1]);
                mma_fp16(acc[1][6], a1, b3[0], b3[1]);
                mma_fp16(acc[0][7], a0, b3[2], b3[3]);
                mma_fp16(acc[1][7], a1, b3[2], b3[3]);
            }
        }

        // Tail for the PREVIOUS tile (uses pacc; fully overlapped with tensor work).
        if (it > 0) {
            const int pt = tile - GRID_SCORE;
            const int pb = pt >> 7;
            const int pt0 = (pt & 127) * TM;
            const float* bq = g_biasq + pb * Un;

            float rowsum[2][2] = {{0.f, 0.f}, {0.f, 0.f}};
#pragma unroll
            for (int nt = 0; nt < 8; ++nt) {
                int c = nwarp * 64 + nt * 8 + 2 * tig;
                float2 bq2 = __ldg((const float2*)(bq + c));
                float2 vv = __ldg((const float2*)(Vw + c));
#pragma unroll
                for (int mt = 0; mt < 2; ++mt) {
                    __half2 x01 = __floats2half2_rn(pacc[mt][nt][0] + bq2.x, pacc[mt][nt][1] + bq2.y);
                    float2 f01 = __half22float2(htanh2(x01));
                    rowsum[mt][0] += f01.x * vv.x + f01.y * vv.y;
                    __half2 x23 = __floats2half2_rn(pacc[mt][nt][2] + bq2.x, pacc[mt][nt][3] + bq2.y);
                    float2 f23 = __half22float2(htanh2(x23));
                    rowsum[mt][1] += f23.x * vv.x + f23.y * vv.y;
                }
            }
#pragma unroll
            for (int mt = 0; mt < 2; ++mt)
#pragma unroll
                for (int j = 0; j < 2; ++j) {
                    float v = rowsum[mt][j];
                    v += __shfl_xor_sync(0xffffffffu, v, 1);
                    v += __shfl_xor_sync(0xffffffffu, v, 2);
                    rowsum[mt][j] = v;
                }
            if (tig == 0) {
#pragma unroll
                for (int mt = 0; mt < 2; ++mt) {
                    int row = mwarp * 32 + mt * 16 + g;
                    srow[row * 4 + nwarp] = rowsum[mt][0];
                    srow[(row + 8) * 4 + nwarp] = rowsum[mt][1];
                }
            }
            __syncthreads();

            if (tid < TM) {
                float4 s4 = *(const float4*)(srow + tid * 4);
                float s = (s4.x + s4.y) + (s4.z + s4.w);
                float es = __expf(s);
                ses[tid] = es;
                g_escore[pb * Tn + pt0 + tid] = es;
                float zs = es;
#pragma unroll
                for (int o = 16; o; o >>= 1) zs += __shfl_xor_sync(0xffffffffu, zs, o);
                if (lane == 0) g_zp[pt * 2 + wid] = zs;
            }
            __syncthreads();

            // Weighted column sum from the prev fp16 tile.
            {
                const uint32_t* sAv = (const uint32_t*)(smem + ((it - 1) & 1) * ABUF_BYTES);
                float2 a2 = make_float2(0.f, 0.f);
#pragma unroll
                for (int j = 0; j < 32; ++j) {
                    int t = grp * 32 + j;
                    float es = ses[t];
                    float2 v = __half22float2(*(const __half2*)&sAv[t * SAW + c2]);
                    a2.x += es * v.x;
                    a2.y += es * v.y;
                }
                spart[grp * 128 + c2] = a2;
            }
            __syncthreads();
            if (grp == 0) {
                float2 p0 = spart[c2], p1 = spart[128 + c2];
                float2 r = make_float2(p0.x + p1.x, p0.y + p1.y);
                *(float2*)(g_partial + (size_t)pt * Dn + 2 * c2) = r;
            }
        }

        // Stage the NEXT tile into buf[(it+1)&1] (safe: tail reads of that buffer
        // finished before the spart barrier above).
        const int tnext = tile + GRID_SCORE;
        if (havec && tnext < NTILES) {
            const float4* v4 = (const float4*)(values + ((size_t)(tnext >> 7) * Tn + (tnext & 127) * TM) * Dn);
            uint2* dst = (uint2*)(smem + ((it + 1) & 1) * ABUF_BYTES);
#pragma unroll
            for (int j = 0; j < 16; ++j) {
                int i = tid + j * 256;
                float4 x = __ldg(v4 + i);
                dst[(i >> 6) * 66 + (i & 63)] = make_uint2(pack_half2(x.x, x.y), pack_half2(x.z, x.w));
            }
        }
        __syncthreads();
    }
}

// ---------------- kernel 2: finalize (Z, weight normalize, context) ----------------

__global__ __launch_bounds__(512)
void finalize_kernel(float* __restrict__ ctx_out, float* __restrict__ w_out) {
    int b = blockIdx.x, tid = threadIdx.x;
    int wid = tid >> 5, lane = tid & 31;
    __shared__ float red[16];
    __shared__ float zsh;
    __shared__ float cpart[512];

    float s = (tid < 256) ? g_zp[b * 256 + tid] : 0.f;
#pragma unroll
    for (int o = 16; o; o >>= 1) s += __shfl_xor_sync(0xffffffffu, s, o);
    if (lane == 0) red[wid] = s;
    __syncthreads();
    if (tid == 0) {
        float z = 0.f;
#pragma unroll
        for (int w = 0; w < 16; ++w) z += red[w];
        zsh = z;
    }
    __syncthreads();
    float invZ = 1.0f / zsh;

    const float4* es4 = (const float4*)(g_escore + (size_t)b * Tn);
    float4* w4 = (float4*)(w_out + (size_t)b * Tn);
#pragma unroll
    for (int j = 0; j < 4; ++j) {
        float4 v = es4[tid + j * 512];
        v.x *= invZ; v.y *= invZ; v.z *= invZ; v.w *= invZ;
        w4[tid + j * 512] = v;
    }

    int half = tid >> 8, d = tid & 255;
    const float* p = g_partial + ((size_t)b * TPB + half * 64) * Dn + d;
    float a = 0.f;
#pragma unroll 8
    for (int c = 0; c < 64; ++c) a += p[(size_t)c * Dn];
    cpart[tid] = a;
    __syncthreads();
    if (tid < 256) ctx_out[b * Dn + tid] = (cpart[tid] + cpart[tid + 256]) * invZ;
}

// ---------------- launch ----------------

extern "C" void kernel_launch(void* const* d_in, const int* in_sizes, int n_in,
                              void* d_out, int out_size) {
    const float* values = (const float*)d_in[0];
    const float* query  = (const float*)d_in[1];
    const float* W1w    = (const float*)d_in[2];
    const float* W1b    = (const float*)d_in[3];
    const float* W2w    = (const float*)d_in[4];
    const float* W2b    = (const float*)d_in[5];
    const float* Vw     = (const float*)d_in[6];
    // d_in[7] = V_b: softmax-invariant constant, intentionally unused.
    (void)in_sizes; (void)n_in; (void)out_size;

    float* ctx_out = (float*)d_out;             // [B, D]
    float* w_out   = (float*)d_out + Bn * Dn;   // [B, T, 1]

    cudaFuncSetAttribute(score_kernel, cudaFuncAttributeMaxDynamicSharedMemorySize, SM_TOTAL);

    projq_kernel<<<dim3(16, Bn), 256>>>(query, W2w, W2b, W1b);
    score_kernel<<<GRID_SCORE, 256, SM_TOTAL>>>(values, W1w, Vw);
    finalize_kernel<<<Bn, 512>>>(ctx_out, w_out);
}

// round 10
// speedup vs baseline: 1.0748x; 1.0748x over previous
#include <cuda_runtime.h>
#include <cuda_fp16.h>
#include <cstdint>
#include <cstddef>

// BahdanauAttention B=16, T=8192, D=256, U=256 fp32.
// Baseline-PTX (ptxas sm_100): fp16 mma.sync + ldmatrix, persistent fused kernel,
// 512 threads. Reordered pipeline: epilogue(prev) -> issue MMA(cur) -> heavy tail
// of prev (exp/Z, weighted context sum) + staging(next) execute while the tensor
// pipe drains the current tile. values read exactly once from DRAM.

#define Bn 16
#define Tn 8192
#define Dn 256
#define Un 256
#define TM 64                       // score tile M
#define TPB 128                     // tiles per batch
#define NTILES (Bn * TPB)           // 2048
#define GRID_SCORE 148

__device__ float g_escore[Bn * Tn];        // exp(score)
__device__ float g_biasq[Bn * Un];
__device__ float g_zp[NTILES * 2];         // per-tile partial sums of exp
__device__ float g_partial[NTILES * Dn];   // per-tile unnormalized context partials

// ---------------- helpers ----------------

__device__ __forceinline__ __half2 htanh2(__half2 x) {
    uint32_t xi = *(uint32_t*)&x, yo;
    asm("tanh.approx.f16x2 %0, %1;" : "=r"(yo) : "r"(xi));
    return *(__half2*)&yo;
}

__device__ __forceinline__ uint32_t pack_half2(float x, float y) {
    __half2 h = __floats2half2_rn(x, y);
    return *(uint32_t*)&h;
}

__device__ __forceinline__ uint32_t smem_u32(const void* p) {
    uint32_t a;
    asm("{ .reg .u64 t; cvta.to.shared.u64 t, %1; cvt.u32.u64 %0, t; }" : "=r"(a) : "l"(p));
    return a;
}

__device__ __forceinline__ void mma_fp16(float* c, const uint32_t* a, uint32_t b0, uint32_t b1) {
    asm volatile(
        "mma.sync.aligned.m16n8k16.row.col.f32.f16.f16.f32 "
        "{%0,%1,%2,%3},{%4,%5,%6,%7},{%8,%9},{%0,%1,%2,%3};"
        : "+f"(c[0]), "+f"(c[1]), "+f"(c[2]), "+f"(c[3])
        : "r"(a[0]), "r"(a[1]), "r"(a[2]), "r"(a[3]), "r"(b0), "r"(b1));
}

#define LDSM4(r, addr) \
    asm volatile("ldmatrix.sync.aligned.m8n8.x4.shared.b16 {%0,%1,%2,%3}, [%4];" \
                 : "=r"((r)[0]), "=r"((r)[1]), "=r"((r)[2]), "=r"((r)[3]) : "r"(addr))

// ---------------- smem layout (bytes) ----------------
#define SAW 132
#define ABUF_BYTES 33792                    // 64 rows x 132 words x 4B
#define SM_B (2 * ABUF_BYTES)               // 67584
#define SM_SROW (SM_B + 135168)             // 202752 : 64 x 8 floats = 2048
#define SM_SES (SM_SROW + 2048)             // 204800 : 64 floats
#define SM_SPART (SM_SES + 256)             // 205056 : 4 x 128 float2 = 4096
#define SM_TOTAL (SM_SPART + 4096)          // 209152

// ---------------- kernel 0: biasq[b,u] = W1_b + W2_b + query@W2 ----------------

__global__ __launch_bounds__(256)
void projq_kernel(const float* __restrict__ query, const float* __restrict__ W2,
                  const float* __restrict__ W2b, const float* __restrict__ W1b) {
    const int b = blockIdx.y;
    const int u0 = blockIdx.x * 16;
    const int tid = threadIdx.x;
    const int ul = tid & 15, dpart = tid >> 4;

    __shared__ float q[Dn];
    __shared__ float part[16][17];

    if (tid < Dn) q[tid] = query[b * Dn + tid];
    __syncthreads();

    const int u = u0 + ul;
    float acc = 0.f;
#pragma unroll
    for (int i = 0; i < 16; ++i) {
        int d = dpart * 16 + i;
        acc += q[d] * __ldg(W2 + (size_t)d * Un + u);
    }
    part[dpart][ul] = acc;
    __syncthreads();

    if (tid < 16) {
        float s = 0.f;
#pragma unroll
        for (int p = 0; p < 16; ++p) s += part[p][tid];
        int uu = u0 + tid;
        g_biasq[b * Un + uu] = s + W2b[uu] + W1b[uu];
    }
}

// ---------------- kernel 1: persistent fused score+context kernel ----------------
// 512 threads (16 warps). Warp (mwarp=wid&1 -> 32 rows, nwarp=wid>>1 -> 32 cols).

__global__ __launch_bounds__(512, 1)
void score_kernel(const float* __restrict__ values, const float* __restrict__ W1,
                  const float* __restrict__ Vw) {
    extern __shared__ char smem[];
    uint32_t* sA = (uint32_t*)smem;
    uint32_t* sB = (uint32_t*)(smem + SM_B);
    float* srow = (float*)(smem + SM_SROW);
    float* ses = (float*)(smem + SM_SES);
    float2* spart = (float2*)(smem + SM_SPART);

    const int tid = threadIdx.x;
    const int wid = tid >> 5, lane = tid & 31;
    const int mwarp = wid & 1, nwarp = wid >> 1;
    const int g = lane >> 2, tig = lane & 3;

    // Stage B once: W1[k][u] -> sB[u][kp] (half2 of k-pair).
#pragma unroll 4
    for (int i = tid; i < 256 * 128; i += 512) {
        int u = i & 255, kp = i >> 8;
        float x0 = __ldg(W1 + (size_t)(2 * kp) * Un + u);
        float x1 = __ldg(W1 + (size_t)(2 * kp + 1) * Un + u);
        sB[u * SAW + kp] = pack_half2(x0, x1);
    }

    // Per-thread Vw pairs for cols c = nwarp*32 + nt*8 + 2tig + {0,1}.
    float2 vw2[4];
#pragma unroll
    for (int nt = 0; nt < 4; ++nt) {
        int c = nwarp * 32 + nt * 8 + 2 * tig;
        vw2[nt] = *(const float2*)(Vw + c);
    }

    const uint32_t sbA = smem_u32(sA), sbB = smem_u32(sB);
    const int t4 = lane >> 3, row_in = lane & 7;
    uint32_t adA[2];
#pragma unroll
    for (int mt = 0; mt < 2; ++mt) {
        int r = mwarp * 32 + mt * 16 + ((t4 & 1) << 3) + row_in;
        adA[mt] = sbA + (uint32_t)((r * SAW + ((t4 >> 1) << 2)) << 2);
    }
    uint32_t adB[2];
#pragma unroll
    for (int np = 0; np < 2; ++np) {
        int u = nwarp * 32 + np * 16 + ((t4 >> 1) << 3) + row_in;
        adB[np] = sbB + (uint32_t)((u * SAW + ((t4 & 1) << 2)) << 2);
    }

    // Prologue: stage first tile into buf0 (float4 loads, uint2 stores).
    {
        const int tile = blockIdx.x;
        const float4* v4 = (const float4*)(values + ((size_t)(tile >> 7) * Tn + (tile & 127) * TM) * Dn);
        uint2* dst = (uint2*)sA;
#pragma unroll
        for (int j = 0; j < 8; ++j) {
            int i = tid + j * 512;
            float4 x = __ldg(v4 + i);
            dst[(i >> 6) * 66 + (i & 63)] = make_uint2(pack_half2(x.x, x.y), pack_half2(x.z, x.w));
        }
    }
    __syncthreads();

    const int c2 = tid & 127, grp = tid >> 7;
    const int ncta = (NTILES - blockIdx.x + GRID_SCORE - 1) / GRID_SCORE;

    float acc[2][4][4];

    for (int it = 0; it <= ncta; ++it) {
        const int tile = blockIdx.x + it * GRID_SCORE;
        const bool havec = it < ncta;
        const int pt = tile - GRID_SCORE;          // previous tile (valid if it>0)
        const int pb = (it > 0) ? (pt >> 7) : 0;
        const int pt0 = (it > 0) ? ((pt & 127) * TM) : 0;

        // 1. Epilogue for previous tile: tanh(acc + biasq) * Vw -> srow.
        //    (acc results drained while prev iteration's tail ran.)
        if (it > 0) {
            const float* bq = g_biasq + pb * Un;
            float rowsum[2][2] = {{0.f, 0.f}, {0.f, 0.f}};
#pragma unroll
            for (int nt = 0; nt < 4; ++nt) {
                int c = nwarp * 32 + nt * 8 + 2 * tig;
                float2 bq2 = __ldg((const float2*)(bq + c));
#pragma unroll
                for (int mt = 0; mt < 2; ++mt) {
                    __half2 x01 = __floats2half2_rn(acc[mt][nt][0] + bq2.x, acc[mt][nt][1] + bq2.y);
                    float2 f01 = __half22float2(htanh2(x01));
                    rowsum[mt][0] += f01.x * vw2[nt].x + f01.y * vw2[nt].y;
                    __half2 x23 = __floats2half2_rn(acc[mt][nt][2] + bq2.x, acc[mt][nt][3] + bq2.y);
                    float2 f23 = __half22float2(htanh2(x23));
                    rowsum[mt][1] += f23.x * vw2[nt].x + f23.y * vw2[nt].y;
                }
            }
#pragma unroll
            for (int mt = 0; mt < 2; ++mt)
#pragma unroll
                for (int j = 0; j < 2; ++j) {
                    float v = rowsum[mt][j];
                    v += __shfl_xor_sync(0xffffffffu, v, 1);
                    v += __shfl_xor_sync(0xffffffffu, v, 2);
                    rowsum[mt][j] = v;
                }
            if (tig == 0) {
#pragma unroll
                for (int mt = 0; mt < 2; ++mt) {
                    int row = mwarp * 32 + mt * 16 + g;
                    srow[row * 8 + nwarp] = rowsum[mt][0];
                    srow[(row + 8) * 8 + nwarp] = rowsum[mt][1];
                }
            }
        }

        // 2+3. Zero acc, issue current tile's MMAs (tensor busy ~8K cyc after this).
        if (havec) {
#pragma unroll
            for (int mt = 0; mt < 2; ++mt)
#pragma unroll
                for (int nt = 0; nt < 4; ++nt)
#pragma unroll
                    for (int q = 0; q < 4; ++q) acc[mt][nt][q] = 0.f;
            const uint32_t abase = (uint32_t)((it & 1) * ABUF_BYTES);
#pragma unroll
            for (int ks = 0; ks < 16; ++ks) {
                const uint32_t ko = (uint32_t)ks * 32;
                uint32_t a0[4], a1[4], b0[4], b1[4];
                LDSM4(a0, adA[0] + abase + ko);
                LDSM4(a1, adA[1] + abase + ko);
                LDSM4(b0, adB[0] + ko);
                LDSM4(b1, adB[1] + ko);
                mma_fp16(acc[0][0], a0, b0[0], b0[1]);
                mma_fp16(acc[1][0], a1, b0[0], b0[1]);
                mma_fp16(acc[0][1], a0, b0[2], b0[3]);
                mma_fp16(acc[1][1], a1, b0[2], b0[3]);
                mma_fp16(acc[0][2], a0, b1[0], b1[1]);
                mma_fp16(acc[1][2], a1, b1[0], b1[1]);
                mma_fp16(acc[0][3], a0, b1[2], b1[3]);
                mma_fp16(acc[1][3], a1, b1[2], b1[3]);
            }
        }

        // 4-6. Heavy tail for previous tile — overlaps with in-flight tensor work.
        if (it > 0) {
            __syncthreads();   // srow visible
            if (tid < TM) {
                const float4* s4 = (const float4*)(srow + tid * 8);
                float4 x = s4[0], y = s4[1];
                float s = ((x.x + x.y) + (x.z + x.w)) + ((y.x + y.y) + (y.z + y.w));
                float es = __expf(s);
                ses[tid] = es;
                g_escore[pb * Tn + pt0 + tid] = es;
                float zs = es;
#pragma unroll
                for (int o = 16; o; o >>= 1) zs += __shfl_xor_sync(0xffffffffu, zs, o);
                if (lane == 0) g_zp[pt * 2 + wid] = zs;
            }
            __syncthreads();   // ses visible

            // Weighted column sum from the PREVIOUS fp16 tile buffer.
            {
                const uint32_t* sAv = (const uint32_t*)(smem + ((it - 1) & 1) * ABUF_BYTES);
                float2 a2 = make_float2(0.f, 0.f);
#pragma unroll
                for (int j = 0; j < 16; ++j) {
                    int t = grp * 16 + j;
                    float es = ses[t];
                    float2 v = __half22float2(*(const __half2*)&sAv[t * SAW + c2]);
                    a2.x += es * v.x;
                    a2.y += es * v.y;
                }
                spart[grp * 128 + c2] = a2;
            }
            __syncthreads();   // spart visible; buf[(it-1)&1] reads complete
            if (grp == 0) {
                float2 p0 = spart[c2], p1 = spart[128 + c2];
                float2 p2 = spart[256 + c2], p3 = spart[384 + c2];
                float2 r;
                r.x = (p0.x + p1.x) + (p2.x + p3.x);
                r.y = (p0.y + p1.y) + (p2.y + p3.y);
                *(float2*)(g_partial + (size_t)pt * Dn + 2 * c2) = r;
            }
        }

        // 7. Stage NEXT tile into buf[(it+1)&1] (== buf[(it-1)&1], safe after the
        //    spart barrier above ended all weighted-sum reads of it).
        const int tnext = tile + GRID_SCORE;
        if (havec && tnext < NTILES) {
            const float4* v4 = (const float4*)(values + ((size_t)(tnext >> 7) * Tn + (tnext & 127) * TM) * Dn);
            uint2* dst = (uint2*)(smem + ((it + 1) & 1) * ABUF_BYTES);
#pragma unroll
            for (int j = 0; j < 8; ++j) {
                int i = tid + j * 512;
                float4 x = __ldg(v4 + i);
                dst[(i >> 6) * 66 + (i & 63)] = make_uint2(pack_half2(x.x, x.y), pack_half2(x.z, x.w));
            }
        }
        __syncthreads();       // staged buffer + srow/ses/spart reuse for next iter
    }
}

// ---------------- kernel 2: finalize (Z, weight normalize, context) ----------------

__global__ __launch_bounds__(512)
void finalize_kernel(float* __restrict__ ctx_out, float* __restrict__ w_out) {
    int b = blockIdx.x, tid = threadIdx.x;
    int wid = tid >> 5, lane = tid & 31;
    __shared__ float red[16];
    __shared__ float zsh;
    __shared__ float cpart[512];

    float s = (tid < 256) ? g_zp[b * 256 + tid] : 0.f;
#pragma unroll
    for (int o = 16; o; o >>= 1) s += __shfl_xor_sync(0xffffffffu, s, o);
    if (lane == 0) red[wid] = s;
    __syncthreads();
    if (tid == 0) {
        float z = 0.f;
#pragma unroll
        for (int w = 0; w < 16; ++w) z += red[w];
        zsh = z;
    }
    __syncthreads();
    float invZ = 1.0f / zsh;

    const float4* es4 = (const float4*)(g_escore + (size_t)b * Tn);
    float4* w4 = (float4*)(w_out + (size_t)b * Tn);
#pragma unroll
    for (int j = 0; j < 4; ++j) {
        float4 v = es4[tid + j * 512];
        v.x *= invZ; v.y *= invZ; v.z *= invZ; v.w *= invZ;
        w4[tid + j * 512] = v;
    }

    int half = tid >> 8, d = tid & 255;
    const float* p = g_partial + ((size_t)b * TPB + half * 64) * Dn + d;
    float a = 0.f;
#pragma unroll 8
    for (int c = 0; c < 64; ++c) a += p[(size_t)c * Dn];
    cpart[tid] = a;
    __syncthreads();
    if (tid < 256) ctx_out[b * Dn + tid] = (cpart[tid] + cpart[tid + 256]) * invZ;
}

// ---------------- launch ----------------

extern "C" void kernel_launch(void* const* d_in, const int* in_sizes, int n_in,
                              void* d_out, int out_size) {
    const float* values = (const float*)d_in[0];
    const float* query  = (const float*)d_in[1];
    const float* W1w    = (const float*)d_in[2];
    const float* W1b    = (const float*)d_in[3];
    const float* W2w    = (const float*)d_in[4];
    const float* W2b    = (const float*)d_in[5];
    const float* Vw     = (const float*)d_in[6];
    // d_in[7] = V_b: softmax-invariant constant, intentionally unused.
    (void)in_sizes; (void)n_in; (void)out_size;

    float* ctx_out = (float*)d_out;             // [B, D]
    float* w_out   = (float*)d_out + Bn * Dn;   // [B, T, 1]

    cudaFuncSetAttribute(score_kernel, cudaFuncAttributeMaxDynamicSharedMemorySize, SM_TOTAL);

    projq_kernel<<<dim3(16, Bn), 256>>>(query, W2w, W2b, W1b);
    score_kernel<<<GRID_SCORE, 512, SM_TOTAL>>>(values, W1w, Vw);
    finalize_kernel<<<Bn, 512>>>(ctx_out, w_out);
}

// round 11
// speedup vs baseline: 1.2055x; 1.1216x over previous
#include <cuda_runtime.h>
#include <cuda_fp16.h>
#include <cstdint>
#include <cstddef>

// BahdanauAttention B=16, T=8192, D=256, U=256 fp32.
// Baseline-PTX (ptxas sm_100): fp16 mma.sync + ldmatrix, persistent fused kernel.
// Two independent 256-thread warp groups per CTA process alternating tiles with
// group-private buffers and NAMED barriers: one group's serial tail/staging runs
// while the other group's HMMAs keep the tensor pipe fed. values read once.

#define Bn 16
#define Tn 8192
#define Dn 256
#define Un 256
#define TM 64                       // score tile M
#define TPB 128                     // tiles per batch
#define NTILES (Bn * TPB)           // 2048
#define GRID_SCORE 148

__device__ float g_escore[Bn * Tn];        // exp(score)
__device__ float g_biasq[Bn * Un];
__device__ float g_zp[NTILES * 2];         // per-tile partial sums of exp
__device__ float g_partial[NTILES * Dn];   // per-tile unnormalized context partials

// ---------------- helpers ----------------

__device__ __forceinline__ __half2 htanh2(__half2 x) {
    uint32_t xi = *(uint32_t*)&x, yo;
    asm("tanh.approx.f16x2 %0, %1;" : "=r"(yo) : "r"(xi));
    return *(__half2*)&yo;
}

__device__ __forceinline__ uint32_t pack_half2(float x, float y) {
    __half2 h = __floats2half2_rn(x, y);
    return *(uint32_t*)&h;
}

__device__ __forceinline__ uint32_t smem_u32(const void* p) {
    uint32_t a;
    asm("{ .reg .u64 t; cvta.to.shared.u64 t, %1; cvt.u32.u64 %0, t; }" : "=r"(a) : "l"(p));
    return a;
}

__device__ __forceinline__ void mma_fp16(float* c, const uint32_t* a, uint32_t b0, uint32_t b1) {
    asm volatile(
        "mma.sync.aligned.m16n8k16.row.col.f32.f16.f16.f32 "
        "{%0,%1,%2,%3},{%4,%5,%6,%7},{%8,%9},{%0,%1,%2,%3};"
        : "+f"(c[0]), "+f"(c[1]), "+f"(c[2]), "+f"(c[3])
        : "r"(a[0]), "r"(a[1]), "r"(a[2]), "r"(a[3]), "r"(b0), "r"(b1));
}

#define LDSM4(r, addr) \
    asm volatile("ldmatrix.sync.aligned.m8n8.x4.shared.b16 {%0,%1,%2,%3}, [%4];" \
                 : "=r"((r)[0]), "=r"((r)[1]), "=r"((r)[2]), "=r"((r)[3]) : "r"(addr))

// Named barrier scoped to one 256-thread warp group (ids 1 and 2; id 0 = __syncthreads).
#define BARG(group) asm volatile("bar.sync %0, 256;" :: "r"((group) + 1) : "memory")

// ---------------- smem layout (bytes) ----------------
#define SAW 132
#define ABUF_BYTES 33792                    // 64 rows x 132 words x 4B
#define SM_B (2 * ABUF_BYTES)               // 67584 ; B ends at 202752
#define SM_GRP 202752                       // per-group scratch: srow 1024 | ses 256 | spart 2048
#define GRP_BYTES 3328
#define SM_TOTAL (SM_GRP + 2 * GRP_BYTES)   // 209408

// ---------------- kernel 0: biasq[b,u] = W1_b + W2_b + query@W2 ----------------

__global__ __launch_bounds__(256)
void projq_kernel(const float* __restrict__ query, const float* __restrict__ W2,
                  const float* __restrict__ W2b, const float* __restrict__ W1b) {
    const int b = blockIdx.y;
    const int u0 = blockIdx.x * 16;
    const int tid = threadIdx.x;
    const int ul = tid & 15, dpart = tid >> 4;

    __shared__ float q[Dn];
    __shared__ float part[16][17];

    if (tid < Dn) q[tid] = query[b * Dn + tid];
    __syncthreads();

    const int u = u0 + ul;
    float acc = 0.f;
#pragma unroll
    for (int i = 0; i < 16; ++i) {
        int d = dpart * 16 + i;
        acc += q[d] * __ldg(W2 + (size_t)d * Un + u);
    }
    part[dpart][ul] = acc;
    __syncthreads();

    if (tid < 16) {
        float s = 0.f;
#pragma unroll
        for (int p = 0; p < 16; ++p) s += part[p][tid];
        int uu = u0 + tid;
        g_biasq[b * Un + uu] = s + W2b[uu] + W1b[uu];
    }
}

// ---------------- kernel 1: persistent fused score+context kernel ----------------
// 512 threads = 2 groups x 8 warps. Group warp (mwarp=gw&1 -> 32 rows,
// nwarp=gw>>1 -> 64 cols): 2 mtiles x 8 ntiles m16n8k16, acc[2][8][4].

__global__ __launch_bounds__(512, 1)
void score_kernel(const float* __restrict__ values, const float* __restrict__ W1,
                  const float* __restrict__ Vw) {
    extern __shared__ char smem[];
    uint32_t* sB = (uint32_t*)(smem + SM_B);

    const int tid = threadIdx.x;
    const int wid = tid >> 5, lane = tid & 31;
    const int group = wid >> 3;                 // 0 or 1
    const int gw = wid & 7;
    const int gtid = tid & 255;
    const int mwarp = gw & 1, nwarp = gw >> 1;  // 32 rows x 64 cols
    const int g = lane >> 2, tig = lane & 3;

    // Stage B once (whole block): W1[k][u] -> sB[u][kp] (half2 of k-pair).
#pragma unroll 4
    for (int i = tid; i < 256 * 128; i += 512) {
        int u = i & 255, kp = i >> 8;
        float x0 = __ldg(W1 + (size_t)(2 * kp) * Un + u);
        float x1 = __ldg(W1 + (size_t)(2 * kp + 1) * Un + u);
        sB[u * SAW + kp] = pack_half2(x0, x1);
    }
    __syncthreads();   // last block-wide barrier; groups are independent below

    // Group-private regions.
    char* agbuf = smem + group * ABUF_BYTES;
    float* srow = (float*)(smem + SM_GRP + group * GRP_BYTES);           // 64 x 4
    float* ses = srow + 256;                                             // 64
    float2* spart = (float2*)(ses + 64);                                 // 2 x 128

    const uint32_t sbA = smem_u32(agbuf), sbB = smem_u32(sB);
    const int t4 = lane >> 3, row_in = lane & 7;
    uint32_t adA[2];
#pragma unroll
    for (int mt = 0; mt < 2; ++mt) {
        int r = mwarp * 32 + mt * 16 + ((t4 & 1) << 3) + row_in;
        adA[mt] = sbA + (uint32_t)((r * SAW + ((t4 >> 1) << 2)) << 2);
    }
    uint32_t adB[4];
#pragma unroll
    for (int np = 0; np < 4; ++np) {
        int u = nwarp * 64 + np * 16 + ((t4 >> 1) << 3) + row_in;
        adB[np] = sbB + (uint32_t)((u * SAW + ((t4 & 1) << 2)) << 2);
    }

    const int c2 = gtid & 127, hh = gtid >> 7;   // weighted-sum mapping (per group)
    const int ncta = (NTILES - blockIdx.x + GRID_SCORE - 1) / GRID_SCORE;

    for (int lt = group; lt < ncta; lt += 2) {
        const int tile = blockIdx.x + lt * GRID_SCORE;
        const int b = tile >> 7;
        const int t0 = (tile & 127) * TM;

        // 1. Stage this group's tile into its private buffer.
        {
            const float4* v4 = (const float4*)(values + ((size_t)b * Tn + t0) * Dn);
            uint2* dst = (uint2*)agbuf;
#pragma unroll 4
            for (int j = 0; j < 16; ++j) {
                int i = gtid + j * 256;
                float4 x = __ldg(v4 + i);
                dst[(i >> 6) * 66 + (i & 63)] = make_uint2(pack_half2(x.x, x.y), pack_half2(x.z, x.w));
            }
        }
        BARG(group);

        // 2. MMA over K=256 (issue-paced; overlaps other group's tail/staging).
        float acc[2][8][4];
#pragma unroll
        for (int mt = 0; mt < 2; ++mt)
#pragma unroll
            for (int nt = 0; nt < 8; ++nt)
#pragma unroll
                for (int q = 0; q < 4; ++q) acc[mt][nt][q] = 0.f;

#pragma unroll
        for (int ks = 0; ks < 16; ++ks) {
            const uint32_t ko = (uint32_t)ks * 32;
            uint32_t a0[4], a1[4], b0[4], b1[4], b2[4], b3[4];
            LDSM4(a0, adA[0] + ko);
            LDSM4(a1, adA[1] + ko);
            LDSM4(b0, adB[0] + ko);
            LDSM4(b1, adB[1] + ko);
            LDSM4(b2, adB[2] + ko);
            LDSM4(b3, adB[3] + ko);
            mma_fp16(acc[0][0], a0, b0[0], b0[1]);
            mma_fp16(acc[1][0], a1, b0[0], b0[1]);
            mma_fp16(acc[0][1], a0, b0[2], b0[3]);
            mma_fp16(acc[1][1], a1, b0[2], b0[3]);
            mma_fp16(acc[0][2], a0, b1[0], b1[1]);
            mma_fp16(acc[1][2], a1, b1[0], b1[1]);
            mma_fp16(acc[0][3], a0, b1[2], b1[3]);
            mma_fp16(acc[1][3], a1, b1[2], b1[3]);
            mma_fp16(acc[0][4], a0, b2[0], b2[1]);
            mma_fp16(acc[1][4], a1, b2[0], b2[1]);
            mma_fp16(acc[0][5], a0, b2[2], b2[3]);
            mma_fp16(acc[1][5], a1, b2[2], b2[3]);
            mma_fp16(acc[0][6], a0, b3[0], b3[1]);
            mma_fp16(acc[1][6], a1, b3[0], b3[1]);
            mma_fp16(acc[0][7], a0, b3[2], b3[3]);
            mma_fp16(acc[1][7], a1, b3[2], b3[3]);
        }

        // 3. Epilogue: tanh(acc + biasq) * Vw -> per-warp row partials.
        {
            const float* bq = g_biasq + b * Un;
            float rowsum[2][2] = {{0.f, 0.f}, {0.f, 0.f}};
#pragma unroll
            for (int nt = 0; nt < 8; ++nt) {
                int c = nwarp * 64 + nt * 8 + 2 * tig;
                float2 bq2 = __ldg((const float2*)(bq + c));
                float2 vv = __ldg((const float2*)(Vw + c));
#pragma unroll
                for (int mt = 0; mt < 2; ++mt) {
                    __half2 x01 = __floats2half2_rn(acc[mt][nt][0] + bq2.x, acc[mt][nt][1] + bq2.y);
                    float2 f01 = __half22float2(htanh2(x01));
                    rowsum[mt][0] += f01.x * vv.x + f01.y * vv.y;
                    __half2 x23 = __floats2half2_rn(acc[mt][nt][2] + bq2.x, acc[mt][nt][3] + bq2.y);
                    float2 f23 = __half22float2(htanh2(x23));
                    rowsum[mt][1] += f23.x * vv.x + f23.y * vv.y;
                }
            }
#pragma unroll
            for (int mt = 0; mt < 2; ++mt)
#pragma unroll
                for (int j = 0; j < 2; ++j) {
                    float v = rowsum[mt][j];
                    v += __shfl_xor_sync(0xffffffffu, v, 1);
                    v += __shfl_xor_sync(0xffffffffu, v, 2);
                    rowsum[mt][j] = v;
                }
            if (tig == 0) {
#pragma unroll
                for (int mt = 0; mt < 2; ++mt) {
                    int row = mwarp * 32 + mt * 16 + g;
                    srow[row * 4 + nwarp] = rowsum[mt][0];
                    srow[(row + 8) * 4 + nwarp] = rowsum[mt][1];
                }
            }
        }
        BARG(group);

        // 4. Final score, exp, per-tile Z partial (first 64 threads of group).
        if (gtid < TM) {
            float4 s4 = *(const float4*)(srow + gtid * 4);
            float s = (s4.x + s4.y) + (s4.z + s4.w);
            float es = __expf(s);
            ses[gtid] = es;
            g_escore[b * Tn + t0 + gtid] = es;
            float zs = es;
#pragma unroll
            for (int o = 16; o; o >>= 1) zs += __shfl_xor_sync(0xffffffffu, zs, o);
            if (lane == 0) g_zp[tile * 2 + (gtid >> 5)] = zs;
        }
        BARG(group);

        // 5. Weighted column sum from the fp16 tile: partial[d] = sum_t es[t]*v[t][d].
        {
            const uint32_t* sAv = (const uint32_t*)agbuf;
            float2 a2 = make_float2(0.f, 0.f);
#pragma unroll
            for (int j = 0; j < 32; ++j) {
                int t = hh * 32 + j;
                float es = ses[t];
                float2 v = __half22float2(*(const __half2*)&sAv[t * SAW + c2]);
                a2.x += es * v.x;
                a2.y += es * v.y;
            }
            spart[hh * 128 + c2] = a2;
        }
        BARG(group);
        if (hh == 0) {
            float2 p0 = spart[c2], p1 = spart[128 + c2];
            float2 r = make_float2(p0.x + p1.x, p0.y + p1.y);
            *(float2*)(g_partial + (size_t)tile * Dn + 2 * c2) = r;
        }
        // No barrier needed before next stage: every thread's own spart/buffer
        // reads precede its stage writes (program order); cross-thread reuse of
        // spart/srow/ses/agbuf is separated by the next iteration's barriers.
        BARG(group);
    }
}

// ---------------- kernel 2: finalize (Z, weight normalize, context) ----------------

__global__ __launch_bounds__(512)
void finalize_kernel(float* __restrict__ ctx_out, float* __restrict__ w_out) {
    int b = blockIdx.x, tid = threadIdx.x;
    int wid = tid >> 5, lane = tid & 31;
    __shared__ float red[16];
    __shared__ float zsh;
    __shared__ float cpart[512];

    float s = (tid < 256) ? g_zp[b * 256 + tid] : 0.f;
#pragma unroll
    for (int o = 16; o; o >>= 1) s += __shfl_xor_sync(0xffffffffu, s, o);
    if (lane == 0) red[wid] = s;
    __syncthreads();
    if (tid == 0) {
        float z = 0.f;
#pragma unroll
        for (int w = 0; w < 16; ++w) z += red[w];
        zsh = z;
    }
    __syncthreads();
    float invZ = 1.0f / zsh;

    const float4* es4 = (const float4*)(g_escore + (size_t)b * Tn);
    float4* w4 = (float4*)(w_out + (size_t)b * Tn);
#pragma unroll
    for (int j = 0; j < 4; ++j) {
        float4 v = es4[tid + j * 512];
        v.x *= invZ; v.y *= invZ; v.z *= invZ; v.w *= invZ;
        w4[tid + j * 512] = v;
    }

    int half = tid >> 8, d = tid & 255;
    const float* p = g_partial + ((size_t)b * TPB + half * 64) * Dn + d;
    float a = 0.f;
#pragma unroll 8
    for (int c = 0; c < 64; ++c) a += p[(size_t)c * Dn];
    cpart[tid] = a;
    __syncthreads();
    if (tid < 256) ctx_out[b * Dn + tid] = (cpart[tid] + cpart[tid + 256]) * invZ;
}

// ---------------- launch ----------------

extern "C" void kernel_launch(void* const* d_in, const int* in_sizes, int n_in,
                              void* d_out, int out_size) {
    const float* values = (const float*)d_in[0];
    const float* query  = (const float*)d_in[1];
    const float* W1w    = (const float*)d_in[2];
    const float* W1b    = (const float*)d_in[3];
    const float* W2w    = (const float*)d_in[4];
    const float* W2b    = (const float*)d_in[5];
    const float* Vw     = (const float*)d_in[6];
    // d_in[7] = V_b: softmax-invariant constant, intentionally unused.
    (void)in_sizes; (void)n_in; (void)out_size;

    float* ctx_out = (float*)d_out;             // [B, D]
    float* w_out   = (float*)d_out + Bn * Dn;   // [B, T, 1]

    cudaFuncSetAttribute(score_kernel, cudaFuncAttributeMaxDynamicSharedMemorySize, SM_TOTAL);

    projq_kernel<<<dim3(16, Bn), 256>>>(query, W2w, W2b, W1b);
    score_kernel<<<GRID_SCORE, 512, SM_TOTAL>>>(values, W1w, Vw);
    finalize_kernel<<<Bn, 512>>>(ctx_out, w_out);
}

// round 12
// speedup vs baseline: 1.2298x; 1.0202x over previous
#include <cuda_runtime.h>
#include <cuda_fp16.h>
#include <cstdint>
#include <cstddef>

// BahdanauAttention B=16, T=8192, D=256, U=256 fp32.
// Baseline-PTX (ptxas sm_100): fp16 mma.sync + ldmatrix, persistent fused kernel:
// score GEMM + tanh(f16x2)*V epilogue + exp + per-tile context partials
// (values read exactly ONCE). projq folded into score kernel as a producer
// pre-phase (CTAs 0..15) with a device flag; reset kernel zeroes the flag.

#define Bn 16
#define Tn 8192
#define Dn 256
#define Un 256
#define TM 64                       // score tile M
#define TPB 128                     // tiles per batch
#define NTILES (Bn * TPB)           // 2048
#define GRID_SCORE 148

__device__ float g_escore[Bn * Tn];        // exp(score)
__device__ float g_biasq[Bn * Un];
__device__ float g_zp[NTILES * 2];         // per-tile partial sums of exp
__device__ float g_partial[NTILES * Dn];   // per-tile unnormalized context partials
__device__ int   g_done;                   // producer-completion flag (reset per launch)

// ---------------- helpers ----------------

__device__ __forceinline__ __half2 htanh2(__half2 x) {
    uint32_t xi = *(uint32_t*)&x, yo;
    asm("tanh.approx.f16x2 %0, %1;" : "=r"(yo) : "r"(xi));
    return *(__half2*)&yo;
}

__device__ __forceinline__ uint32_t pack_half2(float x, float y) {
    __half2 h = __floats2half2_rn(x, y);
    return *(uint32_t*)&h;
}

__device__ __forceinline__ uint32_t smem_u32(const void* p) {
    uint32_t a;
    asm("{ .reg .u64 t; cvta.to.shared.u64 t, %1; cvt.u32.u64 %0, t; }" : "=r"(a) : "l"(p));
    return a;
}

__device__ __forceinline__ void mma_fp16(float* c, const uint32_t* a, uint32_t b0, uint32_t b1) {
    asm volatile(
        "mma.sync.aligned.m16n8k16.row.col.f32.f16.f16.f32 "
        "{%0,%1,%2,%3},{%4,%5,%6,%7},{%8,%9},{%0,%1,%2,%3};"
        : "+f"(c[0]), "+f"(c[1]), "+f"(c[2]), "+f"(c[3])
        : "r"(a[0]), "r"(a[1]), "r"(a[2]), "r"(a[3]), "r"(b0), "r"(b1));
}

#define LDSM4(r, addr) \
    asm volatile("ldmatrix.sync.aligned.m8n8.x4.shared.b16 {%0,%1,%2,%3}, [%4];" \
                 : "=r"((r)[0]), "=r"((r)[1]), "=r"((r)[2]), "=r"((r)[3]) : "r"(addr))

// ---------------- smem layout (bytes) ----------------
#define SAW 132
#define ABUF_BYTES 33792                    // 64 rows x 132 words x 4B
#define SM_B (2 * ABUF_BYTES)               // 67584
#define SM_SROW (SM_B + 135168)             // 202752 : 64 x 8 floats = 2048
#define SM_SES (SM_SROW + 2048)             // 204800 : 64 floats
#define SM_SPART (SM_SES + 256)             // 205056 : 4 x 128 float2 = 4096
#define SM_TOTAL (SM_SPART + 4096)          // 209152

// ---------------- kernel 0: reset flag ----------------

__global__ void reset_kernel() { g_done = 0; }

// ---------------- kernel 1: persistent fused score+context kernel ----------------
// 512 threads (16 warps). Warp (mwarp=wid&1 -> 32 rows, nwarp=wid>>1 -> 32 cols).
// CTAs 0..15 additionally produce biasq[b] (b = blockIdx.x) before their tile loop.

__global__ __launch_bounds__(512, 1)
void score_kernel(const float* __restrict__ values, const float* __restrict__ W1,
                  const float* __restrict__ Vw, const float* __restrict__ query,
                  const float* __restrict__ W2, const float* __restrict__ W2b,
                  const float* __restrict__ W1b) {
    extern __shared__ char smem[];
    uint32_t* sA = (uint32_t*)smem;
    uint32_t* sB = (uint32_t*)(smem + SM_B);
    float* srow = (float*)(smem + SM_SROW);
    float* ses = (float*)(smem + SM_SES);
    float2* spart = (float2*)(smem + SM_SPART);

    const int tid = threadIdx.x;
    const int wid = tid >> 5, lane = tid & 31;
    const int mwarp = wid & 1, nwarp = wid >> 1;
    const int g = lane >> 2, tig = lane & 3;

    // Stage B once: W1[k][u] -> sB[u][kp] (half2 of k-pair).
#pragma unroll 4
    for (int i = tid; i < 256 * 128; i += 512) {
        int u = i & 255, kp = i >> 8;
        float x0 = __ldg(W1 + (size_t)(2 * kp) * Un + u);
        float x1 = __ldg(W1 + (size_t)(2 * kp + 1) * Un + u);
        sB[u * SAW + kp] = pack_half2(x0, x1);
    }

    // Per-thread Vw pairs for cols c = nwarp*32 + nt*8 + 2tig + {0,1}.
    float2 vw2[4];
#pragma unroll
    for (int nt = 0; nt < 4; ++nt) {
        int c = nwarp * 32 + nt * 8 + 2 * tig;
        vw2[nt] = *(const float2*)(Vw + c);
    }

    const uint32_t sbA = smem_u32(sA), sbB = smem_u32(sB);
    const int t4 = lane >> 3, row_in = lane & 7;
    uint32_t adA[2];
#pragma unroll
    for (int mt = 0; mt < 2; ++mt) {
        int r = mwarp * 32 + mt * 16 + ((t4 & 1) << 3) + row_in;
        adA[mt] = sbA + (uint32_t)((r * SAW + ((t4 >> 1) << 2)) << 2);
    }
    uint32_t adB[2];
#pragma unroll
    for (int np = 0; np < 2; ++np) {
        int u = nwarp * 32 + np * 16 + ((t4 >> 1) << 3) + row_in;
        adB[np] = sbB + (uint32_t)((u * SAW + ((t4 & 1) << 2)) << 2);
    }

    // Prologue: stage first tile into buf0 (float4 loads, uint2 stores).
    {
        const int tile = blockIdx.x;
        const float4* v4 = (const float4*)(values + ((size_t)(tile >> 7) * Tn + (tile & 127) * TM) * Dn);
        uint2* dst = (uint2*)sA;
#pragma unroll
        for (int j = 0; j < 8; ++j) {
            int i = tid + j * 512;
            float4 x = __ldg(v4 + i);
            dst[(i >> 6) * 66 + (i & 63)] = make_uint2(pack_half2(x.x, x.y), pack_half2(x.z, x.w));
        }
    }
    __syncthreads();

    // Producer pre-phase: CTA b (b < 16) computes biasq[b, :] then raises g_done.
    // Uses spart (q staging, 1KB) and srow (partials, 2KB) — free until the
    // first epilogue, which is gated on g_done anyway.
    if (blockIdx.x < Bn) {
        const int b = blockIdx.x;
        float* qsh = (float*)spart;               // 256 floats
        float* psh = srow;                        // 512 floats (2 halves x 256 u)
        if (tid < Dn) qsh[tid] = __ldg(query + b * Dn + tid);
        __syncthreads();
        const int u = tid & 255, half = tid >> 8;
        const float* W2c = W2 + (size_t)(half * 128) * Un + u;
        const float* qc = qsh + half * 128;
        float a0 = 0.f, a1 = 0.f, a2 = 0.f, a3 = 0.f;
#pragma unroll 8
        for (int d = 0; d < 128; d += 4) {
            a0 += qc[d] * __ldg(W2c + (size_t)d * Un);
            a1 += qc[d + 1] * __ldg(W2c + (size_t)(d + 1) * Un);
            a2 += qc[d + 2] * __ldg(W2c + (size_t)(d + 2) * Un);
            a3 += qc[d + 3] * __ldg(W2c + (size_t)(d + 3) * Un);
        }
        psh[half * 256 + u] = (a0 + a1) + (a2 + a3);
        __syncthreads();
        if (tid < 256) {
            float s = psh[tid] + psh[256 + tid];
            g_biasq[b * Un + tid] = s + __ldg(W2b + tid) + __ldg(W1b + tid);
        }
        __threadfence();
        __syncthreads();
        if (tid == 0) atomicAdd(&g_done, 1);
    }

    const int c2 = tid & 127, grp = tid >> 7;
    const int ncta = (NTILES - blockIdx.x + GRID_SCORE - 1) / GRID_SCORE;

    int bufi = 0;
    for (int it = 0; it < ncta; ++it) {
        const int tile = blockIdx.x + it * GRID_SCORE;
        const int b = tile >> 7;
        const int t0 = (tile & 127) * TM;
        const int ntile = tile + GRID_SCORE;
        const int has_next = ntile < NTILES;
        const float2* v2n = has_next
            ? (const float2*)(values + ((size_t)(ntile >> 7) * Tn + (ntile & 127) * TM) * Dn)
            : (const float2*)values;
        uint32_t* dst = (uint32_t*)(smem + (bufi ^ 1) * ABUF_BYTES);

        float acc[2][4][4];
#pragma unroll
        for (int mt = 0; mt < 2; ++mt)
#pragma unroll
            for (int nt = 0; nt < 4; ++nt)
#pragma unroll
                for (int q = 0; q < 4; ++q) acc[mt][nt][q] = 0.f;

        // First half prefetch (8 float2 = 16 regs).
        float2 pf[8];
        if (has_next) {
#pragma unroll
            for (int j = 0; j < 8; ++j) pf[j] = __ldg(v2n + tid + j * 512);
        }

        const uint32_t abase = (uint32_t)(bufi * ABUF_BYTES);
#pragma unroll
        for (int ks = 0; ks < 8; ++ks) {
            const uint32_t ko = (uint32_t)ks * 32;
            uint32_t a0[4], a1[4], b0[4], b1[4];
            LDSM4(a0, adA[0] + abase + ko);
            LDSM4(a1, adA[1] + abase + ko);
            LDSM4(b0, adB[0] + ko);
            LDSM4(b1, adB[1] + ko);
            mma_fp16(acc[0][0], a0, b0[0], b0[1]);
            mma_fp16(acc[1][0], a1, b0[0], b0[1]);
            mma_fp16(acc[0][1], a0, b0[2], b0[3]);
            mma_fp16(acc[1][1], a1, b0[2], b0[3]);
            mma_fp16(acc[0][2], a0, b1[0], b1[1]);
            mma_fp16(acc[1][2], a1, b1[0], b1[1]);
            mma_fp16(acc[0][3], a0, b1[2], b1[3]);
            mma_fp16(acc[1][3], a1, b1[2], b1[3]);
        }

        // Store first half, prefetch second half (reuse pf regs).
        if (has_next) {
#pragma unroll
            for (int j = 0; j < 8; ++j) {
                int i = tid + j * 512;
                dst[(i >> 7) * SAW + (i & 127)] = pack_half2(pf[j].x, pf[j].y);
            }
#pragma unroll
            for (int j = 0; j < 8; ++j) pf[j] = __ldg(v2n + tid + (8 + j) * 512);
        }

#pragma unroll
        for (int ks = 8; ks < 16; ++ks) {
            const uint32_t ko = (uint32_t)ks * 32;
            uint32_t a0[4], a1[4], b0[4], b1[4];
            LDSM4(a0, adA[0] + abase + ko);
            LDSM4(a1, adA[1] + abase + ko);
            LDSM4(b0, adB[0] + ko);
            LDSM4(b1, adB[1] + ko);
            mma_fp16(acc[0][0], a0, b0[0], b0[1]);
            mma_fp16(acc[1][0], a1, b0[0], b0[1]);
            mma_fp16(acc[0][1], a0, b0[2], b0[3]);
            mma_fp16(acc[1][1], a1, b0[2], b0[3]);
            mma_fp16(acc[0][2], a0, b1[0], b1[1]);
            mma_fp16(acc[1][2], a1, b1[0], b1[1]);
            mma_fp16(acc[0][3], a0, b1[2], b1[3]);
            mma_fp16(acc[1][3], a1, b1[2], b1[3]);
        }

        if (has_next) {
#pragma unroll
            for (int j = 0; j < 8; ++j) {
                int i = tid + (8 + j) * 512;
                dst[(i >> 7) * SAW + (i & 127)] = pack_half2(pf[j].x, pf[j].y);
            }
        }

        // Gate the FIRST epilogue on producer completion (biasq ready). By now
        // (~1 full MMA tile) producers finished long ago; the wait is ~free.
        if (it == 0) {
            if (tid == 0) {
                while (atomicAdd(&g_done, 0) < Bn) __nanosleep(64);
            }
            __syncthreads();
            __threadfence();
        }

        // Epilogue: tanh(f16x2) of fp32-biased sums, fp32 product accumulation.
        const float* bq = g_biasq + b * Un;
        float rowsum[2][2] = {{0.f, 0.f}, {0.f, 0.f}};
#pragma unroll
        for (int nt = 0; nt < 4; ++nt) {
            int c = nwarp * 32 + nt * 8 + 2 * tig;
            float2 bq2 = __ldg((const float2*)(bq + c));
#pragma unroll
            for (int mt = 0; mt < 2; ++mt) {
                __half2 x01 = __floats2half2_rn(acc[mt][nt][0] + bq2.x, acc[mt][nt][1] + bq2.y);
                float2 f01 = __half22float2(htanh2(x01));
                rowsum[mt][0] += f01.x * vw2[nt].x + f01.y * vw2[nt].y;
                __half2 x23 = __floats2half2_rn(acc[mt][nt][2] + bq2.x, acc[mt][nt][3] + bq2.y);
                float2 f23 = __half22float2(htanh2(x23));
                rowsum[mt][1] += f23.x * vw2[nt].x + f23.y * vw2[nt].y;
            }
        }
#pragma unroll
        for (int mt = 0; mt < 2; ++mt)
#pragma unroll
            for (int j = 0; j < 2; ++j) {
                float v = rowsum[mt][j];
                v += __shfl_xor_sync(0xffffffffu, v, 1);
                v += __shfl_xor_sync(0xffffffffu, v, 2);
                rowsum[mt][j] = v;
            }
        if (tig == 0) {
#pragma unroll
            for (int mt = 0; mt < 2; ++mt) {
                int row = mwarp * 32 + mt * 16 + g;
                srow[row * 8 + nwarp] = rowsum[mt][0];
                srow[(row + 8) * 8 + nwarp] = rowsum[mt][1];
            }
        }
        __syncthreads();

        // Rows 0..63: final score, exp, per-tile Z partial.
        if (tid < TM) {
            const float4* s4 = (const float4*)(srow + tid * 8);
            float4 x = s4[0], y = s4[1];
            float s = ((x.x + x.y) + (x.z + x.w)) + ((y.x + y.y) + (y.z + y.w));
            float es = __expf(s);
            ses[tid] = es;
            g_escore[b * Tn + t0 + tid] = es;
            float zs = es;
#pragma unroll
            for (int o = 16; o; o >>= 1) zs += __shfl_xor_sync(0xffffffffu, zs, o);
            if (lane == 0) g_zp[tile * 2 + wid] = zs;
        }
        __syncthreads();

        // Weighted column sum from the fp16 tile: partial[d] = sum_t es[t]*v[t][d].
        {
            const uint32_t* sAv = (const uint32_t*)(smem + bufi * ABUF_BYTES);
            float2 a2 = make_float2(0.f, 0.f);
#pragma unroll
            for (int j = 0; j < 16; ++j) {
                int t = grp * 16 + j;
                float es = ses[t];
                float2 v = __half22float2(*(const __half2*)&sAv[t * SAW + c2]);
                a2.x += es * v.x;
                a2.y += es * v.y;
            }
            spart[grp * 128 + c2] = a2;
        }
        __syncthreads();
        if (grp == 0) {
            float2 p0 = spart[c2], p1 = spart[128 + c2];
            float2 p2 = spart[256 + c2], p3 = spart[384 + c2];
            float2 r;
            r.x = (p0.x + p1.x) + (p2.x + p3.x);
            r.y = (p0.y + p1.y) + (p2.y + p3.y);
            *(float2*)(g_partial + (size_t)tile * Dn + 2 * c2) = r;
        }
        // NOTE: no sync needed here. grp0's spart reads precede the next tile's
        // spart writes (separated by next tile's srow sync); this tile's sA[bufi]
        // weighted-sum reads precede next tile's STS to the same buffer (separated
        // by the spart sync above).
        bufi ^= 1;
    }
}

// ---------------- kernel 2: finalize (Z, weight normalize, context) ----------------

__global__ __launch_bounds__(512)
void finalize_kernel(float* __restrict__ ctx_out, float* __restrict__ w_out) {
    int b = blockIdx.x, tid = threadIdx.x;
    int wid = tid >> 5, lane = tid & 31;
    __shared__ float red[16];
    __shared__ float zsh;
    __shared__ float cpart[512];

    float s = (tid < 256) ? g_zp[b * 256 + tid] : 0.f;
#pragma unroll
    for (int o = 16; o; o >>= 1) s += __shfl_xor_sync(0xffffffffu, s, o);
    if (lane == 0) red[wid] = s;
    __syncthreads();
    if (tid == 0) {
        float z = 0.f;
#pragma unroll
        for (int w = 0; w < 16; ++w) z += red[w];
        zsh = z;
    }
    __syncthreads();
    float invZ = 1.0f / zsh;

    const float4* es4 = (const float4*)(g_escore + (size_t)b * Tn);
    float4* w4 = (float4*)(w_out + (size_t)b * Tn);
#pragma unroll
    for (int j = 0; j < 4; ++j) {
        float4 v = es4[tid + j * 512];
        v.x *= invZ; v.y *= invZ; v.z *= invZ; v.w *= invZ;
        w4[tid + j * 512] = v;
    }

    int half = tid >> 8, d = tid & 255;
    const float* p = g_partial + ((size_t)b * TPB + half * 64) * Dn + d;
    float a = 0.f;
#pragma unroll 8
    for (int c = 0; c < 64; ++c) a += p[(size_t)c * Dn];
    cpart[tid] = a;
    __syncthreads();
    if (tid < 256) ctx_out[b * Dn + tid] = (cpart[tid] + cpart[tid + 256]) * invZ;
}

// ---------------- launch ----------------

extern "C" void kernel_launch(void* const* d_in, const int* in_sizes, int n_in,
                              void* d_out, int out_size) {
    const float* values = (const float*)d_in[0];
    const float* query  = (const float*)d_in[1];
    const float* W1w    = (const float*)d_in[2];
    const float* W1b    = (const float*)d_in[3];
    const float* W2w    = (const float*)d_in[4];
    const float* W2b    = (const float*)d_in[5];
    const float* Vw     = (const float*)d_in[6];
    // d_in[7] = V_b: softmax-invariant constant, intentionally unused.
    (void)in_sizes; (void)n_in; (void)out_size;

    float* ctx_out = (float*)d_out;             // [B, D]
    float* w_out   = (float*)d_out + Bn * Dn;   // [B, T, 1]

    cudaFuncSetAttribute(score_kernel, cudaFuncAttributeMaxDynamicSharedMemorySize, SM_TOTAL);

    reset_kernel<<<1, 1>>>();
    score_kernel<<<GRID_SCORE, 512, SM_TOTAL>>>(values, W1w, Vw, query, W2w, W2b, W1b);
    finalize_kernel<<<Bn, 512>>>(ctx_out, w_out);
}

// round 13
// speedup vs baseline: 1.2824x; 1.0428x over previous
#include <cuda_runtime.h>
#include <cuda_fp16.h>
#include <cstdint>
#include <cstddef>

// BahdanauAttention B=16, T=8192, D=256, U=256 fp32.
// Baseline-PTX (ptxas sm_100): fp16 mma.sync + ldmatrix, persistent fused kernel:
// score GEMM + tanh(f16x2)*V epilogue + exp + per-tile context partials
// (values read exactly ONCE). biasq produced by 128 CTAs inside score kernel;
// completion flag reset by finalize (no reset kernel). 2 launches total.

#define Bn 16
#define Tn 8192
#define Dn 256
#define Un 256
#define TM 64                       // score tile M
#define TPB 128                     // tiles per batch
#define NTILES (Bn * TPB)           // 2048
#define GRID_SCORE 148
#define NPROD 128                   // producer CTAs (8 per batch)

__device__ float g_escore[Bn * Tn];        // exp(score)
__device__ float g_biasq[Bn * Un];
__device__ float g_zp[NTILES * 2];         // per-tile partial sums of exp
__device__ float g_partial[NTILES * Dn];   // per-tile unnormalized context partials
__device__ int   g_done;                   // producer flag; finalize resets to 0

// ---------------- helpers ----------------

__device__ __forceinline__ __half2 htanh2(__half2 x) {
    uint32_t xi = *(uint32_t*)&x, yo;
    asm("tanh.approx.f16x2 %0, %1;" : "=r"(yo) : "r"(xi));
    return *(__half2*)&yo;
}

__device__ __forceinline__ uint32_t pack_half2(float x, float y) {
    __half2 h = __floats2half2_rn(x, y);
    return *(uint32_t*)&h;
}

__device__ __forceinline__ uint32_t smem_u32(const void* p) {
    uint32_t a;
    asm("{ .reg .u64 t; cvta.to.shared.u64 t, %1; cvt.u32.u64 %0, t; }" : "=r"(a) : "l"(p));
    return a;
}

__device__ __forceinline__ void mma_fp16(float* c, const uint32_t* a, uint32_t b0, uint32_t b1) {
    asm volatile(
        "mma.sync.aligned.m16n8k16.row.col.f32.f16.f16.f32 "
        "{%0,%1,%2,%3},{%4,%5,%6,%7},{%8,%9},{%0,%1,%2,%3};"
        : "+f"(c[0]), "+f"(c[1]), "+f"(c[2]), "+f"(c[3])
        : "r"(a[0]), "r"(a[1]), "r"(a[2]), "r"(a[3]), "r"(b0), "r"(b1));
}

#define LDSM4(r, addr) \
    asm volatile("ldmatrix.sync.aligned.m8n8.x4.shared.b16 {%0,%1,%2,%3}, [%4];" \
                 : "=r"((r)[0]), "=r"((r)[1]), "=r"((r)[2]), "=r"((r)[3]) : "r"(addr))

// ---------------- smem layout (bytes) ----------------
#define SAW 132
#define ABUF_BYTES 33792                    // 64 rows x 132 words x 4B
#define SM_B (2 * ABUF_BYTES)               // 67584
#define SM_SROW (SM_B + 135168)             // 202752 : 64 x 8 floats = 2048
#define SM_SES (SM_SROW + 2048)             // 204800 : 64 floats
#define SM_SPART (SM_SES + 256)             // 205056 : 4 x 128 float2 = 4096
#define SM_TOTAL (SM_SPART + 4096)          // 209152

// ---------------- kernel 1: persistent fused score+context kernel ----------------
// 512 threads (16 warps). Warp (mwarp=wid&1 -> 32 rows, nwarp=wid>>1 -> 32 cols).
// CTAs 0..127 each produce 32 biasq columns of one batch before their tile loop.

__global__ __launch_bounds__(512, 1)
void score_kernel(const float* __restrict__ values, const float* __restrict__ W1,
                  const float* __restrict__ Vw, const float* __restrict__ query,
                  const float* __restrict__ W2, const float* __restrict__ W2b,
                  const float* __restrict__ W1b) {
    extern __shared__ char smem[];
    uint32_t* sA = (uint32_t*)smem;
    uint32_t* sB = (uint32_t*)(smem + SM_B);
    float* srow = (float*)(smem + SM_SROW);
    float* ses = (float*)(smem + SM_SES);
    float2* spart = (float2*)(smem + SM_SPART);

    const int tid = threadIdx.x;
    const int wid = tid >> 5, lane = tid & 31;
    const int mwarp = wid & 1, nwarp = wid >> 1;
    const int g = lane >> 2, tig = lane & 3;

    // Stage B once: W1[k][u] -> sB[u][kp] (half2 of k-pair).
#pragma unroll 4
    for (int i = tid; i < 256 * 128; i += 512) {
        int u = i & 255, kp = i >> 8;
        float x0 = __ldg(W1 + (size_t)(2 * kp) * Un + u);
        float x1 = __ldg(W1 + (size_t)(2 * kp + 1) * Un + u);
        sB[u * SAW + kp] = pack_half2(x0, x1);
    }

    // Per-thread Vw pairs for cols c = nwarp*32 + nt*8 + 2tig + {0,1}.
    float2 vw2[4];
#pragma unroll
    for (int nt = 0; nt < 4; ++nt) {
        int c = nwarp * 32 + nt * 8 + 2 * tig;
        vw2[nt] = *(const float2*)(Vw + c);
    }

    const uint32_t sbA = smem_u32(sA), sbB = smem_u32(sB);
    const int t4 = lane >> 3, row_in = lane & 7;
    uint32_t adA[2];
#pragma unroll
    for (int mt = 0; mt < 2; ++mt) {
        int r = mwarp * 32 + mt * 16 + ((t4 & 1) << 3) + row_in;
        adA[mt] = sbA + (uint32_t)((r * SAW + ((t4 >> 1) << 2)) << 2);
    }
    uint32_t adB[2];
#pragma unroll
    for (int np = 0; np < 2; ++np) {
        int u = nwarp * 32 + np * 16 + ((t4 >> 1) << 3) + row_in;
        adB[np] = sbB + (uint32_t)((u * SAW + ((t4 & 1) << 2)) << 2);
    }

    // Prologue: stage first tile into buf0 (float4 loads, uint2 stores).
    {
        const int tile = blockIdx.x;
        const float4* v4 = (const float4*)(values + ((size_t)(tile >> 7) * Tn + (tile & 127) * TM) * Dn);
        uint2* dst = (uint2*)sA;
#pragma unroll
        for (int j = 0; j < 8; ++j) {
            int i = tid + j * 512;
            float4 x = __ldg(v4 + i);
            dst[(i >> 6) * 66 + (i & 63)] = make_uint2(pack_half2(x.x, x.y), pack_half2(x.z, x.w));
        }
    }
    __syncthreads();

    // Producer pre-phase: CTA k (k < 128) computes biasq[b, u0:u0+32) for
    // b = k>>3, u0 = (k&7)*32, then raises g_done. Per thread: 16 loads only.
    // Uses spart (q staging) and srow (partials) — free until the first epilogue.
    if (blockIdx.x < NPROD) {
        const int b = blockIdx.x >> 3;
        const int u0 = (blockIdx.x & 7) * 32;
        float* qsh = (float*)spart;               // 256 floats
        float* psh = srow;                        // 16 x 32 floats
        if (tid < Dn) qsh[tid] = __ldg(query + b * Dn + tid);
        __syncthreads();
        const int ul = tid & 31, dp = tid >> 5;   // 16 d-parts x 16 d each
        const float* W2c = W2 + (size_t)(dp * 16) * Un + u0 + ul;
        const float* qc = qsh + dp * 16;
        float a0 = 0.f, a1 = 0.f, a2 = 0.f, a3 = 0.f;
#pragma unroll
        for (int d = 0; d < 16; d += 4) {
            a0 += qc[d] * __ldg(W2c + (size_t)d * Un);
            a1 += qc[d + 1] * __ldg(W2c + (size_t)(d + 1) * Un);
            a2 += qc[d + 2] * __ldg(W2c + (size_t)(d + 2) * Un);
            a3 += qc[d + 3] * __ldg(W2c + (size_t)(d + 3) * Un);
        }
        psh[dp * 32 + ul] = (a0 + a1) + (a2 + a3);
        __syncthreads();
        if (tid < 32) {
            float s = 0.f;
#pragma unroll
            for (int p = 0; p < 16; ++p) s += psh[p * 32 + tid];
            int uu = u0 + tid;
            g_biasq[b * Un + uu] = s + __ldg(W2b + uu) + __ldg(W1b + uu);
        }
        __threadfence();
        __syncthreads();
        if (tid == 0) atomicAdd(&g_done, 1);
    }

    const int c2 = tid & 127, grp = tid >> 7;
    const int ncta = (NTILES - blockIdx.x + GRID_SCORE - 1) / GRID_SCORE;

    int bufi = 0;
    for (int it = 0; it < ncta; ++it) {
        const int tile = blockIdx.x + it * GRID_SCORE;
        const int b = tile >> 7;
        const int t0 = (tile & 127) * TM;
        const int ntile = tile + GRID_SCORE;
        const int has_next = ntile < NTILES;
        const float2* v2n = has_next
            ? (const float2*)(values + ((size_t)(ntile >> 7) * Tn + (ntile & 127) * TM) * Dn)
            : (const float2*)values;
        uint32_t* dst = (uint32_t*)(smem + (bufi ^ 1) * ABUF_BYTES);

        float acc[2][4][4];
#pragma unroll
        for (int mt = 0; mt < 2; ++mt)
#pragma unroll
            for (int nt = 0; nt < 4; ++nt)
#pragma unroll
                for (int q = 0; q < 4; ++q) acc[mt][nt][q] = 0.f;

        // First half prefetch (8 float2 = 16 regs).
        float2 pf[8];
        if (has_next) {
#pragma unroll
            for (int j = 0; j < 8; ++j) pf[j] = __ldg(v2n + tid + j * 512);
        }

        const uint32_t abase = (uint32_t)(bufi * ABUF_BYTES);
#pragma unroll
        for (int ks = 0; ks < 8; ++ks) {
            const uint32_t ko = (uint32_t)ks * 32;
            uint32_t a0[4], a1[4], b0[4], b1[4];
            LDSM4(a0, adA[0] + abase + ko);
            LDSM4(a1, adA[1] + abase + ko);
            LDSM4(b0, adB[0] + ko);
            LDSM4(b1, adB[1] + ko);
            mma_fp16(acc[0][0], a0, b0[0], b0[1]);
            mma_fp16(acc[1][0], a1, b0[0], b0[1]);
            mma_fp16(acc[0][1], a0, b0[2], b0[3]);
            mma_fp16(acc[1][1], a1, b0[2], b0[3]);
            mma_fp16(acc[0][2], a0, b1[0], b1[1]);
            mma_fp16(acc[1][2], a1, b1[0], b1[1]);
            mma_fp16(acc[0][3], a0, b1[2], b1[3]);
            mma_fp16(acc[1][3], a1, b1[2], b1[3]);
        }

        // Store first half, prefetch second half (reuse pf regs).
        if (has_next) {
#pragma unroll
            for (int j = 0; j < 8; ++j) {
                int i = tid + j * 512;
                dst[(i >> 7) * SAW + (i & 127)] = pack_half2(pf[j].x, pf[j].y);
            }
#pragma unroll
            for (int j = 0; j < 8; ++j) pf[j] = __ldg(v2n + tid + (8 + j) * 512);
        }

#pragma unroll
        for (int ks = 8; ks < 16; ++ks) {
            const uint32_t ko = (uint32_t)ks * 32;
            uint32_t a0[4], a1[4], b0[4], b1[4];
            LDSM4(a0, adA[0] + abase + ko);
            LDSM4(a1, adA[1] + abase + ko);
            LDSM4(b0, adB[0] + ko);
            LDSM4(b1, adB[1] + ko);
            mma_fp16(acc[0][0], a0, b0[0], b0[1]);
            mma_fp16(acc[1][0], a1, b0[0], b0[1]);
            mma_fp16(acc[0][1], a0, b0[2], b0[3]);
            mma_fp16(acc[1][1], a1, b0[2], b0[3]);
            mma_fp16(acc[0][2], a0, b1[0], b1[1]);
            mma_fp16(acc[1][2], a1, b1[0], b1[1]);
            mma_fp16(acc[0][3], a0, b1[2], b1[3]);
            mma_fp16(acc[1][3], a1, b1[2], b1[3]);
        }

        if (has_next) {
#pragma unroll
            for (int j = 0; j < 8; ++j) {
                int i = tid + (8 + j) * 512;
                dst[(i >> 7) * SAW + (i & 127)] = pack_half2(pf[j].x, pf[j].y);
            }
        }

        // Gate the FIRST epilogue on producer completion (biasq ready). By now
        // (~1 full MMA tile) producers finished; the wait is ~free.
        if (it == 0) {
            if (tid == 0) {
                while (atomicAdd(&g_done, 0) < NPROD) __nanosleep(64);
            }
            __syncthreads();
            __threadfence();
        }

        // Epilogue: tanh(f16x2) of fp32-biased sums, fp32 product accumulation.
        const float* bq = g_biasq + b * Un;
        float rowsum[2][2] = {{0.f, 0.f}, {0.f, 0.f}};
#pragma unroll
        for (int nt = 0; nt < 4; ++nt) {
            int c = nwarp * 32 + nt * 8 + 2 * tig;
            float2 bq2 = __ldg((const float2*)(bq + c));
#pragma unroll
            for (int mt = 0; mt < 2; ++mt) {
                __half2 x01 = __floats2half2_rn(acc[mt][nt][0] + bq2.x, acc[mt][nt][1] + bq2.y);
                float2 f01 = __half22float2(htanh2(x01));
                rowsum[mt][0] += f01.x * vw2[nt].x + f01.y * vw2[nt].y;
                __half2 x23 = __floats2half2_rn(acc[mt][nt][2] + bq2.x, acc[mt][nt][3] + bq2.y);
                float2 f23 = __half22float2(htanh2(x23));
                rowsum[mt][1] += f23.x * vw2[nt].x + f23.y * vw2[nt].y;
            }
        }
#pragma unroll
        for (int mt = 0; mt < 2; ++mt)
#pragma unroll
            for (int j = 0; j < 2; ++j) {
                float v = rowsum[mt][j];
                v += __shfl_xor_sync(0xffffffffu, v, 1);
                v += __shfl_xor_sync(0xffffffffu, v, 2);
                rowsum[mt][j] = v;
            }
        if (tig == 0) {
#pragma unroll
            for (int mt = 0; mt < 2; ++mt) {
                int row = mwarp * 32 + mt * 16 + g;
                srow[row * 8 + nwarp] = rowsum[mt][0];
                srow[(row + 8) * 8 + nwarp] = rowsum[mt][1];
            }
        }
        __syncthreads();

        // Rows 0..63: final score, exp, per-tile Z partial.
        if (tid < TM) {
            const float4* s4 = (const float4*)(srow + tid * 8);
            float4 x = s4[0], y = s4[1];
            float s = ((x.x + x.y) + (x.z + x.w)) + ((y.x + y.y) + (y.z + y.w));
            float es = __expf(s);
            ses[tid] = es;
            g_escore[b * Tn + t0 + tid] = es;
            float zs = es;
#pragma unroll
            for (int o = 16; o; o >>= 1) zs += __shfl_xor_sync(0xffffffffu, zs, o);
            if (lane == 0) g_zp[tile * 2 + wid] = zs;
        }
        __syncthreads();

        // Weighted column sum from the fp16 tile: partial[d] = sum_t es[t]*v[t][d].
        {
            const uint32_t* sAv = (const uint32_t*)(smem + bufi * ABUF_BYTES);
            float2 a2 = make_float2(0.f, 0.f);
#pragma unroll
            for (int j = 0; j < 16; ++j) {
                int t = grp * 16 + j;
                float es = ses[t];
                float2 v = __half22float2(*(const __half2*)&sAv[t * SAW + c2]);
                a2.x += es * v.x;
                a2.y += es * v.y;
            }
            spart[grp * 128 + c2] = a2;
        }
        __syncthreads();
        if (grp == 0) {
            float2 p0 = spart[c2], p1 = spart[128 + c2];
            float2 p2 = spart[256 + c2], p3 = spart[384 + c2];
            float2 r;
            r.x = (p0.x + p1.x) + (p2.x + p3.x);
            r.y = (p0.y + p1.y) + (p2.y + p3.y);
            *(float2*)(g_partial + (size_t)tile * Dn + 2 * c2) = r;
        }
        // NOTE: no sync needed here (see prior-round analysis).
        bufi ^= 1;
    }
}

// ---------------- kernel 2: finalize (Z, weight normalize, context, flag reset) ----

__global__ __launch_bounds__(512)
void finalize_kernel(float* __restrict__ ctx_out, float* __restrict__ w_out) {
    int b = blockIdx.x, tid = threadIdx.x;
    int wid = tid >> 5, lane = tid & 31;
    __shared__ float red[16];
    __shared__ float zsh;
    __shared__ float cpart[512];

    // Reset producer flag for the next launch/replay (score finished already).
    if (b == 0 && tid == 0) g_done = 0;

    float s = (tid < 256) ? g_zp[b * 256 + tid] : 0.f;
#pragma unroll
    for (int o = 16; o; o >>= 1) s += __shfl_xor_sync(0xffffffffu, s, o);
    if (lane == 0) red[wid] = s;
    __syncthreads();
    if (tid == 0) {
        float z = 0.f;
#pragma unroll
        for (int w = 0; w < 16; ++w) z += red[w];
        zsh = z;
    }
    __syncthreads();
    float invZ = 1.0f / zsh;

    const float4* es4 = (const float4*)(g_escore + (size_t)b * Tn);
    float4* w4 = (float4*)(w_out + (size_t)b * Tn);
#pragma unroll
    for (int j = 0; j < 4; ++j) {
        float4 v = es4[tid + j * 512];
        v.x *= invZ; v.y *= invZ; v.z *= invZ; v.w *= invZ;
        w4[tid + j * 512] = v;
    }

    int half = tid >> 8, d = tid & 255;
    const float* p = g_partial + ((size_t)b * TPB + half * 64) * Dn + d;
    float a = 0.f;
#pragma unroll 8
    for (int c = 0; c < 64; ++c) a += p[(size_t)c * Dn];
    cpart[tid] = a;
    __syncthreads();
    if (tid < 256) ctx_out[b * Dn + tid] = (cpart[tid] + cpart[tid + 256]) * invZ;
}

// ---------------- launch ----------------

extern "C" void kernel_launch(void* const* d_in, const int* in_sizes, int n_in,
                              void* d_out, int out_size) {
    const float* values = (const float*)d_in[0];
    const float* query  = (const float*)d_in[1];
    const float* W1w    = (const float*)d_in[2];
    const float* W1b    = (const float*)d_in[3];
    const float* W2w    = (const float*)d_in[4];
    const float* W2b    = (const float*)d_in[5];
    const float* Vw     = (const float*)d_in[6];
    // d_in[7] = V_b: softmax-invariant constant, intentionally unused.
    (void)in_sizes; (void)n_in; (void)out_size;

    float* ctx_out = (float*)d_out;             // [B, D]
    float* w_out   = (float*)d_out + Bn * Dn;   // [B, T, 1]

    cudaFuncSetAttribute(score_kernel, cudaFuncAttributeMaxDynamicSharedMemorySize, SM_TOTAL);

    score_kernel<<<GRID_SCORE, 512, SM_TOTAL>>>(values, W1w, Vw, query, W2w, W2b, W1b);
    finalize_kernel<<<Bn, 512>>>(ctx_out, w_out);
}

// round 14
// speedup vs baseline: 1.3421x; 1.0465x over previous
#include <cuda_runtime.h>
#include <cuda_fp16.h>
#include <cstdint>
#include <cstddef>

// BahdanauAttention B=16, T=8192, D=256, U=256 fp32.
// Baseline-PTX (ptxas sm_100): fp16 mma.sync + ldmatrix, persistent fused kernel:
// score GEMM + tanh(f16x2)*V epilogue + exp + per-tile context partials
// (values read exactly ONCE). biasq produced by 128 CTAs inside score kernel;
// wide finalize (128 blocks) computes Z/weights/context. 2 launches total.

#define Bn 16
#define Tn 8192
#define Dn 256
#define Un 256
#define TM 64                       // score tile M
#define TPB 128                     // tiles per batch
#define NTILES (Bn * TPB)           // 2048
#define GRID_SCORE 148
#define NPROD 128                   // producer CTAs (8 per batch)

__device__ float g_escore[Bn * Tn];        // exp(score)
__device__ float g_biasq[Bn * Un];
__device__ float g_zp[NTILES * 2];         // per-tile partial sums of exp
__device__ float g_partial[NTILES * Dn];   // per-tile unnormalized context partials
__device__ int   g_done;                   // producer flag; finalize resets to 0

// ---------------- helpers ----------------

__device__ __forceinline__ __half2 htanh2(__half2 x) {
    uint32_t xi = *(uint32_t*)&x, yo;
    asm("tanh.approx.f16x2 %0, %1;" : "=r"(yo) : "r"(xi));
    return *(__half2*)&yo;
}

__device__ __forceinline__ uint32_t pack_half2(float x, float y) {
    __half2 h = __floats2half2_rn(x, y);
    return *(uint32_t*)&h;
}

__device__ __forceinline__ uint32_t smem_u32(const void* p) {
    uint32_t a;
    asm("{ .reg .u64 t; cvta.to.shared.u64 t, %1; cvt.u32.u64 %0, t; }" : "=r"(a) : "l"(p));
    return a;
}

__device__ __forceinline__ void mma_fp16(float* c, const uint32_t* a, uint32_t b0, uint32_t b1) {
    asm volatile(
        "mma.sync.aligned.m16n8k16.row.col.f32.f16.f16.f32 "
        "{%0,%1,%2,%3},{%4,%5,%6,%7},{%8,%9},{%0,%1,%2,%3};"
        : "+f"(c[0]), "+f"(c[1]), "+f"(c[2]), "+f"(c[3])
        : "r"(a[0]), "r"(a[1]), "r"(a[2]), "r"(a[3]), "r"(b0), "r"(b1));
}

#define LDSM4(r, addr) \
    asm volatile("ldmatrix.sync.aligned.m8n8.x4.shared.b16 {%0,%1,%2,%3}, [%4];" \
                 : "=r"((r)[0]), "=r"((r)[1]), "=r"((r)[2]), "=r"((r)[3]) : "r"(addr))

// ---------------- smem layout (bytes) ----------------
#define SAW 132
#define ABUF_BYTES 33792                    // 64 rows x 132 words x 4B
#define SM_B (2 * ABUF_BYTES)               // 67584
#define SM_SROW (SM_B + 135168)             // 202752 : 64 x 8 floats = 2048
#define SM_SES (SM_SROW + 2048)             // 204800 : 64 floats
#define SM_SPART (SM_SES + 256)             // 205056 : 4 x 128 float2 = 4096
#define SM_TOTAL (SM_SPART + 4096)          // 209152

// ---------------- kernel 1: persistent fused score+context kernel ----------------
// 512 threads (16 warps). Warp (mwarp=wid&1 -> 32 rows, nwarp=wid>>1 -> 32 cols).
// CTAs 0..127 each produce 32 biasq columns of one batch before their tile loop.

__global__ __launch_bounds__(512, 1)
void score_kernel(const float* __restrict__ values, const float* __restrict__ W1,
                  const float* __restrict__ Vw, const float* __restrict__ query,
                  const float* __restrict__ W2, const float* __restrict__ W2b,
                  const float* __restrict__ W1b) {
    extern __shared__ char smem[];
    uint32_t* sA = (uint32_t*)smem;
    uint32_t* sB = (uint32_t*)(smem + SM_B);
    float* srow = (float*)(smem + SM_SROW);
    float* ses = (float*)(smem + SM_SES);
    float2* spart = (float2*)(smem + SM_SPART);

    const int tid = threadIdx.x;
    const int wid = tid >> 5, lane = tid & 31;
    const int mwarp = wid & 1, nwarp = wid >> 1;
    const int g = lane >> 2, tig = lane & 3;

    // Stage B once: W1[k][u] -> sB[u][kp] (half2 of k-pair).
#pragma unroll 4
    for (int i = tid; i < 256 * 128; i += 512) {
        int u = i & 255, kp = i >> 8;
        float x0 = __ldg(W1 + (size_t)(2 * kp) * Un + u);
        float x1 = __ldg(W1 + (size_t)(2 * kp + 1) * Un + u);
        sB[u * SAW + kp] = pack_half2(x0, x1);
    }

    // Per-thread Vw pairs for cols c = nwarp*32 + nt*8 + 2tig + {0,1}.
    float2 vw2[4];
#pragma unroll
    for (int nt = 0; nt < 4; ++nt) {
        int c = nwarp * 32 + nt * 8 + 2 * tig;
        vw2[nt] = *(const float2*)(Vw + c);
    }

    const uint32_t sbA = smem_u32(sA), sbB = smem_u32(sB);
    const int t4 = lane >> 3, row_in = lane & 7;
    uint32_t adA[2];
#pragma unroll
    for (int mt = 0; mt < 2; ++mt) {
        int r = mwarp * 32 + mt * 16 + ((t4 & 1) << 3) + row_in;
        adA[mt] = sbA + (uint32_t)((r * SAW + ((t4 >> 1) << 2)) << 2);
    }
    uint32_t adB[2];
#pragma unroll
    for (int np = 0; np < 2; ++np) {
        int u = nwarp * 32 + np * 16 + ((t4 >> 1) << 3) + row_in;
        adB[np] = sbB + (uint32_t)((u * SAW + ((t4 & 1) << 2)) << 2);
    }

    // Prologue: stage first tile into buf0 (float4 loads, uint2 stores).
    {
        const int tile = blockIdx.x;
        const float4* v4 = (const float4*)(values + ((size_t)(tile >> 7) * Tn + (tile & 127) * TM) * Dn);
        uint2* dst = (uint2*)sA;
#pragma unroll
        for (int j = 0; j < 8; ++j) {
            int i = tid + j * 512;
            float4 x = __ldg(v4 + i);
            dst[(i >> 6) * 66 + (i & 63)] = make_uint2(pack_half2(x.x, x.y), pack_half2(x.z, x.w));
        }
    }
    __syncthreads();

    // Producer pre-phase: CTA k (k < 128) computes biasq[b, u0:u0+32) for
    // b = k>>3, u0 = (k&7)*32, then raises g_done. Per thread: 16 loads only.
    if (blockIdx.x < NPROD) {
        const int b = blockIdx.x >> 3;
        const int u0 = (blockIdx.x & 7) * 32;
        float* qsh = (float*)spart;               // 256 floats
        float* psh = srow;                        // 16 x 32 floats
        if (tid < Dn) qsh[tid] = __ldg(query + b * Dn + tid);
        __syncthreads();
        const int ul = tid & 31, dp = tid >> 5;   // 16 d-parts x 16 d each
        const float* W2c = W2 + (size_t)(dp * 16) * Un + u0 + ul;
        const float* qc = qsh + dp * 16;
        float a0 = 0.f, a1 = 0.f, a2 = 0.f, a3 = 0.f;
#pragma unroll
        for (int d = 0; d < 16; d += 4) {
            a0 += qc[d] * __ldg(W2c + (size_t)d * Un);
            a1 += qc[d + 1] * __ldg(W2c + (size_t)(d + 1) * Un);
            a2 += qc[d + 2] * __ldg(W2c + (size_t)(d + 2) * Un);
            a3 += qc[d + 3] * __ldg(W2c + (size_t)(d + 3) * Un);
        }
        psh[dp * 32 + ul] = (a0 + a1) + (a2 + a3);
        __syncthreads();
        if (tid < 32) {
            float s = 0.f;
#pragma unroll
            for (int p = 0; p < 16; ++p) s += psh[p * 32 + tid];
            int uu = u0 + tid;
            g_biasq[b * Un + uu] = s + __ldg(W2b + uu) + __ldg(W1b + uu);
        }
        __threadfence();
        __syncthreads();
        if (tid == 0) atomicAdd(&g_done, 1);
    }

    const int c2 = tid & 127, grp = tid >> 7;
    const int ncta = (NTILES - blockIdx.x + GRID_SCORE - 1) / GRID_SCORE;

    int bufi = 0;
    for (int it = 0; it < ncta; ++it) {
        const int tile = blockIdx.x + it * GRID_SCORE;
        const int b = tile >> 7;
        const int t0 = (tile & 127) * TM;
        const int ntile = tile + GRID_SCORE;
        const int has_next = ntile < NTILES;
        const float2* v2n = has_next
            ? (const float2*)(values + ((size_t)(ntile >> 7) * Tn + (ntile & 127) * TM) * Dn)
            : (const float2*)values;
        uint32_t* dst = (uint32_t*)(smem + (bufi ^ 1) * ABUF_BYTES);

        float acc[2][4][4];
#pragma unroll
        for (int mt = 0; mt < 2; ++mt)
#pragma unroll
            for (int nt = 0; nt < 4; ++nt)
#pragma unroll
                for (int q = 0; q < 4; ++q) acc[mt][nt][q] = 0.f;

        // First half prefetch (8 float2 = 16 regs).
        float2 pf[8];
        if (has_next) {
#pragma unroll
            for (int j = 0; j < 8; ++j) pf[j] = __ldg(v2n + tid + j * 512);
        }

        const uint32_t abase = (uint32_t)(bufi * ABUF_BYTES);
#pragma unroll
        for (int ks = 0; ks < 8; ++ks) {
            const uint32_t ko = (uint32_t)ks * 32;
            uint32_t a0[4], a1[4], b0[4], b1[4];
            LDSM4(a0, adA[0] + abase + ko);
            LDSM4(a1, adA[1] + abase + ko);
            LDSM4(b0, adB[0] + ko);
            LDSM4(b1, adB[1] + ko);
            mma_fp16(acc[0][0], a0, b0[0], b0[1]);
            mma_fp16(acc[1][0], a1, b0[0], b0[1]);
            mma_fp16(acc[0][1], a0, b0[2], b0[3]);
            mma_fp16(acc[1][1], a1, b0[2], b0[3]);
            mma_fp16(acc[0][2], a0, b1[0], b1[1]);
            mma_fp16(acc[1][2], a1, b1[0], b1[1]);
            mma_fp16(acc[0][3], a0, b1[2], b1[3]);
            mma_fp16(acc[1][3], a1, b1[2], b1[3]);
        }

        // Store first half, prefetch second half (reuse pf regs).
        if (has_next) {
#pragma unroll
            for (int j = 0; j < 8; ++j) {
                int i = tid + j * 512;
                dst[(i >> 7) * SAW + (i & 127)] = pack_half2(pf[j].x, pf[j].y);
            }
#pragma unroll
            for (int j = 0; j < 8; ++j) pf[j] = __ldg(v2n + tid + (8 + j) * 512);
        }

#pragma unroll
        for (int ks = 8; ks < 16; ++ks) {
            const uint32_t ko = (uint32_t)ks * 32;
            uint32_t a0[4], a1[4], b0[4], b1[4];
            LDSM4(a0, adA[0] + abase + ko);
            LDSM4(a1, adA[1] + abase + ko);
            LDSM4(b0, adB[0] + ko);
            LDSM4(b1, adB[1] + ko);
            mma_fp16(acc[0][0], a0, b0[0], b0[1]);
            mma_fp16(acc[1][0], a1, b0[0], b0[1]);
            mma_fp16(acc[0][1], a0, b0[2], b0[3]);
            mma_fp16(acc[1][1], a1, b0[2], b0[3]);
            mma_fp16(acc[0][2], a0, b1[0], b1[1]);
            mma_fp16(acc[1][2], a1, b1[0], b1[1]);
            mma_fp16(acc[0][3], a0, b1[2], b1[3]);
            mma_fp16(acc[1][3], a1, b1[2], b1[3]);
        }

        if (has_next) {
#pragma unroll
            for (int j = 0; j < 8; ++j) {
                int i = tid + (8 + j) * 512;
                dst[(i >> 7) * SAW + (i & 127)] = pack_half2(pf[j].x, pf[j].y);
            }
        }

        // Gate the FIRST epilogue on producer completion (biasq ready).
        if (it == 0) {
            if (tid == 0) {
                while (atomicAdd(&g_done, 0) < NPROD) __nanosleep(64);
            }
            __syncthreads();
            __threadfence();
        }

        // Epilogue: tanh(f16x2) of fp32-biased sums, fp32 product accumulation.
        const float* bq = g_biasq + b * Un;
        float rowsum[2][2] = {{0.f, 0.f}, {0.f, 0.f}};
#pragma unroll
        for (int nt = 0; nt < 4; ++nt) {
            int c = nwarp * 32 + nt * 8 + 2 * tig;
            float2 bq2 = __ldg((const float2*)(bq + c));
#pragma unroll
            for (int mt = 0; mt < 2; ++mt) {
                __half2 x01 = __floats2half2_rn(acc[mt][nt][0] + bq2.x, acc[mt][nt][1] + bq2.y);
                float2 f01 = __half22float2(htanh2(x01));
                rowsum[mt][0] += f01.x * vw2[nt].x + f01.y * vw2[nt].y;
                __half2 x23 = __floats2half2_rn(acc[mt][nt][2] + bq2.x, acc[mt][nt][3] + bq2.y);
                float2 f23 = __half22float2(htanh2(x23));
                rowsum[mt][1] += f23.x * vw2[nt].x + f23.y * vw2[nt].y;
            }
        }
#pragma unroll
        for (int mt = 0; mt < 2; ++mt)
#pragma unroll
            for (int j = 0; j < 2; ++j) {
                float v = rowsum[mt][j];
                v += __shfl_xor_sync(0xffffffffu, v, 1);
                v += __shfl_xor_sync(0xffffffffu, v, 2);
                rowsum[mt][j] = v;
            }
        if (tig == 0) {
#pragma unroll
            for (int mt = 0; mt < 2; ++mt) {
                int row = mwarp * 32 + mt * 16 + g;
                srow[row * 8 + nwarp] = rowsum[mt][0];
                srow[(row + 8) * 8 + nwarp] = rowsum[mt][1];
            }
        }
        __syncthreads();

        // Rows 0..63: final score, exp, per-tile Z partial.
        if (tid < TM) {
            const float4* s4 = (const float4*)(srow + tid * 8);
            float4 x = s4[0], y = s4[1];
            float s = ((x.x + x.y) + (x.z + x.w)) + ((y.x + y.y) + (y.z + y.w));
            float es = __expf(s);
            ses[tid] = es;
            g_escore[b * Tn + t0 + tid] = es;
            float zs = es;
#pragma unroll
            for (int o = 16; o; o >>= 1) zs += __shfl_xor_sync(0xffffffffu, zs, o);
            if (lane == 0) g_zp[tile * 2 + wid] = zs;
        }
        __syncthreads();

        // Weighted column sum from the fp16 tile: partial[d] = sum_t es[t]*v[t][d].
        {
            const uint32_t* sAv = (const uint32_t*)(smem + bufi * ABUF_BYTES);
            float2 a2 = make_float2(0.f, 0.f);
#pragma unroll
            for (int j = 0; j < 16; ++j) {
                int t = grp * 16 + j;
                float es = ses[t];
                float2 v = __half22float2(*(const __half2*)&sAv[t * SAW + c2]);
                a2.x += es * v.x;
                a2.y += es * v.y;
            }
            spart[grp * 128 + c2] = a2;
        }
        __syncthreads();
        if (grp == 0) {
            float2 p0 = spart[c2], p1 = spart[128 + c2];
            float2 p2 = spart[256 + c2], p3 = spart[384 + c2];
            float2 r;
            r.x = (p0.x + p1.x) + (p2.x + p3.x);
            r.y = (p0.y + p1.y) + (p2.y + p3.y);
            *(float2*)(g_partial + (size_t)tile * Dn + 2 * c2) = r;
        }
        // NOTE: no sync needed here (see prior-round analysis).
        bufi ^= 1;
    }
}

// ---------------- kernel 2: wide finalize (Z, weights, context, flag reset) ------
// Grid (8, 16) x 256 threads. Block (j, b): Z from per-tile partials (redundant
// across j), weight slice [j*1024, +1024), context d-slice [j*32, +32) with
// 8-way tile parallelism per column.

__global__ __launch_bounds__(256)
void finalize_kernel(float* __restrict__ ctx_out, float* __restrict__ w_out) {
    const int j = blockIdx.x, b = blockIdx.y;
    const int tid = threadIdx.x;
    const int wid = tid >> 5, lane = tid & 31;
    __shared__ float red[8];
    __shared__ float zsh;
    __shared__ float cpart[8][32];

    if (j == 0 && b == 0 && tid == 0) g_done = 0;   // reset producer flag

    // Z[b] = sum of 256 per-tile partials (same reduction order as before).
    float s = g_zp[b * 256 + tid];
#pragma unroll
    for (int o = 16; o; o >>= 1) s += __shfl_xor_sync(0xffffffffu, s, o);
    if (lane == 0) red[wid] = s;
    __syncthreads();
    if (tid == 0) {
        float z = 0.f;
#pragma unroll
        for (int w = 0; w < 8; ++w) z += red[w];
        zsh = z;
    }
    __syncthreads();
    const float invZ = 1.0f / zsh;

    // Normalize weight slice: 1024 elems = 1 float4 per thread.
    {
        int i = j * 256 + tid;
        float4 v = ((const float4*)(g_escore + (size_t)b * Tn))[i];
        v.x *= invZ; v.y *= invZ; v.z *= invZ; v.w *= invZ;
        ((float4*)(w_out + (size_t)b * Tn))[i] = v;
    }

    // Context d-slice [j*32, +32): 8 tile-parts x 16 tiles each, smem reduce.
    {
        const int ul = tid & 31, p = tid >> 5;
        const float* pp = g_partial + ((size_t)b * TPB + p * 16) * Dn + j * 32 + ul;
        float a = 0.f;
#pragma unroll
        for (int c = 0; c < 16; ++c) a += pp[(size_t)c * Dn];
        cpart[p][ul] = a;
        __syncthreads();
        if (tid < 32) {
            float t = 0.f;
#pragma unroll
            for (int p2 = 0; p2 < 8; ++p2) t += cpart[p2][tid];
            ctx_out[b * Dn + j * 32 + tid] = t * invZ;
        }
    }
}

// ---------------- launch ----------------

extern "C" void kernel_launch(void* const* d_in, const int* in_sizes, int n_in,
                              void* d_out, int out_size) {
    const float* values = (const float*)d_in[0];
    const float* query  = (const float*)d_in[1];
    const float* W1w    = (const float*)d_in[2];
    const float* W1b    = (const float*)d_in[3];
    const float* W2w    = (const float*)d_in[4];
    const float* W2b    = (const float*)d_in[5];
    const float* Vw     = (const float*)d_in[6];
    // d_in[7] = V_b: softmax-invariant constant, intentionally unused.
    (void)in_sizes; (void)n_in; (void)out_size;

    float* ctx_out = (float*)d_out;             // [B, D]
    float* w_out   = (float*)d_out + Bn * Dn;   // [B, T, 1]

    cudaFuncSetAttribute(score_kernel, cudaFuncAttributeMaxDynamicSharedMemorySize, SM_TOTAL);

    score_kernel<<<GRID_SCORE, 512, SM_TOTAL>>>(values, W1w, Vw, query, W2w, W2b, W1b);
    finalize_kernel<<<dim3(8, Bn), 256>>>(ctx_out, w_out);
}